// round 10
// baseline (speedup 1.0000x reference)
#include <cuda_runtime.h>

#define BATCH 32
#define SEQ   4096

typedef unsigned long long ull;

// ---------------- packed f32x2 helpers ----------------
__device__ __forceinline__ void fma2(ull& d, ull a, ull b) {
    asm("fma.rn.f32x2 %0, %1, %2, %0;" : "+l"(d) : "l"(a), "l"(b));
}
__device__ __forceinline__ float2 upk(ull v) {
    float2 f;
    asm("mov.b64 {%0, %1}, %2;" : "=f"(f.x), "=f"(f.y) : "l"(v));
    return f;
}

// ---------------- device scratch (no allocation) ----------------
// transposed first-layer weights: [k][token][o]
__device__ __align__(16) float g_wT_h[12][128][64];
__device__ __align__(16) float g_wT_m[5][128][64];
__device__ __align__(16) float g_wT_d[4][6][16];
__device__ __align__(16) float g_wT_r[8][32];

// transposed second-layer weights: [o][k][c]
__device__ __align__(16) float g_w2_h[32][8][64];
__device__ __align__(16) float g_w2_m[32][3][64];
__device__ __align__(16) float g_w2_r[64][4][32];
__device__ __align__(16) float g_w2_d[16][3][16];

// pooled partials
__device__ float g_part_r[BATCH][16][64];   // 16 chunks of 64 out-l
__device__ float g_part_h[BATCH][32][32];   // 32 chunks of 64 out-l
__device__ float g_part_m[BATCH][32][32];   // 32 chunks of 128 out-l
__device__ float g_dpool [BATCH][128][16];
__device__ __align__(16) float g_feats[BATCH][512];

// ---------------- weight prep (tiny) ----------------
__global__ void prep_kernel(const float* __restrict__ r1w, const float* __restrict__ r2w,
                            const float* __restrict__ h1w, const float* __restrict__ h2w,
                            const float* __restrict__ m1w, const float* __restrict__ m2w,
                            const float* __restrict__ d1w, const float* __restrict__ d2w) {
    int stride = gridDim.x * blockDim.x;
    int tid = blockIdx.x * blockDim.x + threadIdx.x;
    for (int i = tid; i < 64*128*12; i += stride) {
        int o = i / (128*12), r = i % (128*12), t = r / 12, k = r % 12;
        g_wT_h[k][t][o] = h1w[i];
    }
    for (int i = tid; i < 64*128*5; i += stride) {
        int o = i / 640, r = i % 640, t = r / 5, k = r % 5;
        g_wT_m[k][t][o] = m1w[i];
    }
    for (int i = tid; i < 16*6*4; i += stride) {
        int o = i / 24, r = i % 24, v = r / 4, k = r % 4;
        g_wT_d[k][v][o] = d1w[i];
    }
    for (int i = tid; i < 32*8; i += stride) {
        int o = i / 8, k = i % 8;
        g_wT_r[k][o] = r1w[i];
    }
    for (int i = tid; i < 32*64*8; i += stride) {
        int o = i / 512, r = i % 512, c = r / 8, k = r % 8;
        g_w2_h[o][k][c] = h2w[i];
    }
    for (int i = tid; i < 32*64*3; i += stride) {
        int o = i / 192, r = i % 192, c = r / 3, k = r % 3;
        g_w2_m[o][k][c] = m2w[i];
    }
    for (int i = tid; i < 64*32*4; i += stride) {
        int o = i / 128, r = i % 128, c = r / 4, k = r % 4;
        g_w2_r[o][k][c] = r2w[i];
    }
    for (int i = tid; i < 16*16*3; i += stride) {
        int o = i / 48, r = i % 48, c = r / 3, k = r % 3;
        g_w2_d[o][k][c] = d2w[i];
    }
}

// ---------------- fused branch mega-kernel ----------------
// blocks [0,1024): harmony   (b, chunk of 64 out-l;  32 chunks)
// blocks [1024,2048): melody (b, chunk of 128 out-l; 32 chunks)
// blocks [2048,2560): rhythm (b, chunk of 64 out-l;  16 chunks)
// blocks [2560,3584): dynamics (b, group of 4 q-bins; 32 groups)
__global__ void __launch_bounds__(256) branches_kernel(
    const int* __restrict__ tok,
    const float* __restrict__ r1b, const float* __restrict__ r2b,
    const float* __restrict__ h1b, const float* __restrict__ h2b,
    const float* __restrict__ m1b, const float* __restrict__ m2b,
    const float* __restrict__ d1b, const float* __restrict__ d2b)
{
    __shared__ __align__(16) float s_x[8576];   // conv1 tile, [pos][C]
    __shared__ __align__(16) float s_aux[272];  // tokens / ts window
    const int tid = threadIdx.x;
    const int bid = blockIdx.x;
    const int lane = tid & 31;
    const int wrp  = tid >> 5;

    if (bid < 1024) {
        // ================= HARMONY =================
        const int b = bid >> 5, chunk = bid & 31;
        const int L0 = chunk * 64;
        const int P0 = 2 * L0 - 3;          // conv1 pos base, 134 positions
        int* stok = (int*)s_aux;
        for (int j = tid; j < 145; j += 256) {
            int p = P0 - 6 + j;
            stok[j] = ((unsigned)p < (unsigned)SEQ) ? tok[b * SEQ + p] : -1;
        }
        __syncthreads();
        // conv1 into smem: 134 pos x 64 ch
        for (int t = tid; t < 134 * 16; t += 256) {
            int i = t >> 4, o4 = t & 15;
            int p = P0 + i;
            float4 acc = make_float4(0.f, 0.f, 0.f, 0.f);
            if ((unsigned)p < 4097u) {
                acc = __ldg(reinterpret_cast<const float4*>(h1b) + o4);
                #pragma unroll
                for (int k = 0; k < 12; k++) {
                    int tkn = stok[i + k];
                    if ((unsigned)tkn < 128u) {
                        float4 w = *reinterpret_cast<const float4*>(&g_wT_h[k][tkn][o4 * 4]);
                        acc.x += w.x; acc.y += w.y; acc.z += w.z; acc.w += w.w;
                    }
                }
                acc.x = fmaxf(acc.x, 0.f); acc.y = fmaxf(acc.y, 0.f);
                acc.z = fmaxf(acc.z, 0.f); acc.w = fmaxf(acc.w, 0.f);
            }
            *reinterpret_cast<float4*>(&s_x[(i * 16 + o4) * 4]) = acc;
        }
        __syncthreads();
        // conv2: lane -> 2 l, warp -> 4 o. i = 4*lane + 2d + k.
        const int ob = wrp * 4;
        const int ib = 4 * lane;
        ull acc[4][2] = {{0,0},{0,0},{0,0},{0,0}};
        #pragma unroll
        for (int c4 = 0; c4 < 16; c4++) {
            ulonglong2 in[10];
            #pragma unroll
            for (int r = 0; r < 10; r++)
                in[r] = *reinterpret_cast<const ulonglong2*>(&s_x[((ib + r) * 16 + c4) * 4]);
            #pragma unroll
            for (int k = 0; k < 8; k++) {
                #pragma unroll
                for (int o = 0; o < 4; o++) {
                    ulonglong2 ww = __ldg(reinterpret_cast<const ulonglong2*>(&g_w2_h[ob + o][k][c4 * 4]));
                    fma2(acc[o][0], ww.x, in[k].x);
                    fma2(acc[o][0], ww.y, in[k].y);
                    fma2(acc[o][1], ww.x, in[k + 2].x);
                    fma2(acc[o][1], ww.y, in[k + 2].y);
                }
            }
        }
        #pragma unroll
        for (int o = 0; o < 4; o++) {
            float bo = __ldg(h2b + ob + o);
            float2 f0 = upk(acc[o][0]), f1 = upk(acc[o][1]);
            float s = fmaxf(f0.x + f0.y + bo, 0.f) + fmaxf(f1.x + f1.y + bo, 0.f);
            #pragma unroll
            for (int off = 16; off > 0; off >>= 1)
                s += __shfl_down_sync(0xffffffffu, s, off);
            if (lane == 0) g_part_h[b][chunk][ob + o] = s;
        }
    } else if (bid < 2048) {
        // ================= MELODY =================
        const int idx = bid - 1024;
        const int b = idx >> 5, chunk = idx & 31;
        const int L0 = chunk * 128;
        const int P0 = L0 - 1;              // 130 positions
        int* stok = (int*)s_aux;
        for (int j = tid; j < 134; j += 256) {
            int p = P0 - 2 + j;
            stok[j] = ((unsigned)p < (unsigned)SEQ) ? tok[b * SEQ + p] : -1;
        }
        __syncthreads();
        for (int t = tid; t < 130 * 16; t += 256) {
            int i = t >> 4, o4 = t & 15;
            int p = P0 + i;
            float4 acc = make_float4(0.f, 0.f, 0.f, 0.f);
            if ((unsigned)p < 4096u) {
                acc = __ldg(reinterpret_cast<const float4*>(m1b) + o4);
                #pragma unroll
                for (int k = 0; k < 5; k++) {
                    int tkn = stok[i + k];
                    if ((unsigned)tkn < 128u) {
                        float4 w = *reinterpret_cast<const float4*>(&g_wT_m[k][tkn][o4 * 4]);
                        acc.x += w.x; acc.y += w.y; acc.z += w.z; acc.w += w.w;
                    }
                }
                acc.x = fmaxf(acc.x, 0.f); acc.y = fmaxf(acc.y, 0.f);
                acc.z = fmaxf(acc.z, 0.f); acc.w = fmaxf(acc.w, 0.f);
            }
            *reinterpret_cast<float4*>(&s_x[(i * 16 + o4) * 4]) = acc;
        }
        __syncthreads();
        // conv2: lane -> 4 l, warp -> 4 o. i = 4*lane + d + k.
        const int ob = wrp * 4;
        const int ib = 4 * lane;
        ull acc[4][4] = {};
        #pragma unroll
        for (int c4 = 0; c4 < 16; c4++) {
            ulonglong2 in[7];
            #pragma unroll
            for (int r = 0; r < 7; r++)
                in[r] = *reinterpret_cast<const ulonglong2*>(&s_x[((ib + r) * 16 + c4) * 4]);
            #pragma unroll
            for (int k = 0; k < 3; k++) {
                #pragma unroll
                for (int o = 0; o < 4; o++) {
                    ulonglong2 ww = __ldg(reinterpret_cast<const ulonglong2*>(&g_w2_m[ob + o][k][c4 * 4]));
                    #pragma unroll
                    for (int d = 0; d < 4; d++) {
                        fma2(acc[o][d], ww.x, in[k + d].x);
                        fma2(acc[o][d], ww.y, in[k + d].y);
                    }
                }
            }
        }
        #pragma unroll
        for (int o = 0; o < 4; o++) {
            float bo = __ldg(m2b + ob + o);
            float s = 0.f;
            #pragma unroll
            for (int d = 0; d < 4; d++) {
                float2 f = upk(acc[o][d]);
                s += fmaxf(f.x + f.y + bo, 0.f);
            }
            #pragma unroll
            for (int off = 16; off > 0; off >>= 1)
                s += __shfl_down_sync(0xffffffffu, s, off);
            if (lane == 0) g_part_m[b][chunk][ob + o] = s;
        }
    } else if (bid < 2560) {
        // ================= RHYTHM =================
        const int idx = bid - 2048;
        const int b = idx >> 4, chunk = idx & 15;
        const int L0 = chunk * 64;
        const int P0 = 2 * L0 - 1;          // 131 r1 positions
        const int T0 = 2 * P0 - 3;          // ts window base, 268 values
        for (int j = tid; j < 268; j += 256) {
            int tp = T0 + j;
            float v = 0.f;
            if ((unsigned)tp < (unsigned)SEQ) {
                int t = tok[b * SEQ + tp];
                v = (t >= 256 && t < 768) ? 1.f : 0.f;
            }
            s_aux[j] = v;
        }
        __syncthreads();
        // r1 conv into smem: 131 pos x 32 ch
        for (int t = tid; t < 131 * 8; t += 256) {
            int i = t >> 3, o4 = t & 7;
            int p = P0 + i;
            float4 acc = make_float4(0.f, 0.f, 0.f, 0.f);
            if ((unsigned)p < 2048u) {
                acc = __ldg(reinterpret_cast<const float4*>(r1b) + o4);
                #pragma unroll
                for (int k = 0; k < 8; k++) {
                    float tv = s_aux[2 * i + k];
                    float4 w = *reinterpret_cast<const float4*>(&g_wT_r[k][o4 * 4]);
                    acc.x = fmaf(tv, w.x, acc.x);
                    acc.y = fmaf(tv, w.y, acc.y);
                    acc.z = fmaf(tv, w.z, acc.z);
                    acc.w = fmaf(tv, w.w, acc.w);
                }
                acc.x = fmaxf(acc.x, 0.f); acc.y = fmaxf(acc.y, 0.f);
                acc.z = fmaxf(acc.z, 0.f); acc.w = fmaxf(acc.w, 0.f);
            }
            *reinterpret_cast<float4*>(&s_x[(i * 8 + o4) * 4]) = acc;
        }
        __syncthreads();
        // conv2: lane -> 2 l, warp -> 8 o. i = 4*lane + 2d + k, k in [0,4).
        const int ob = wrp * 8;
        const int ib = 4 * lane;
        ull acc[8][2] = {};
        #pragma unroll
        for (int c4 = 0; c4 < 8; c4++) {
            ulonglong2 in[6];
            #pragma unroll
            for (int r = 0; r < 6; r++)
                in[r] = *reinterpret_cast<const ulonglong2*>(&s_x[((ib + r) * 8 + c4) * 4]);
            #pragma unroll
            for (int k = 0; k < 4; k++) {
                #pragma unroll
                for (int o = 0; o < 8; o++) {
                    ulonglong2 ww = __ldg(reinterpret_cast<const ulonglong2*>(&g_w2_r[ob + o][k][c4 * 4]));
                    fma2(acc[o][0], ww.x, in[k].x);
                    fma2(acc[o][0], ww.y, in[k].y);
                    fma2(acc[o][1], ww.x, in[k + 2].x);
                    fma2(acc[o][1], ww.y, in[k + 2].y);
                }
            }
        }
        #pragma unroll
        for (int o = 0; o < 8; o++) {
            float bo = __ldg(r2b + ob + o);
            float2 f0 = upk(acc[o][0]), f1 = upk(acc[o][1]);
            float s = fmaxf(f0.x + f0.y + bo, 0.f) + fmaxf(f1.x + f1.y + bo, 0.f);
            #pragma unroll
            for (int off = 16; off > 0; off >>= 1)
                s += __shfl_down_sync(0xffffffffu, s, off);
            if (lane == 0) g_part_r[b][chunk][ob + o] = s;
        }
    } else {
        // ================= DYNAMICS =================
        const int idx = bid - 2560;
        const int b = idx >> 5, qg = idx & 31;
        const int q0 = qg * 4;
        const int s_all = (q0 * 4097) >> 7;
        const int e_all = ((q0 + 4) * 4097 + 127) >> 7;
        const int P0 = s_all - 1;
        const int PN = e_all - s_all + 2;   // <= 131
        int* stok = (int*)s_aux;
        for (int j = tid; j < PN + 3; j += 256) {
            int p = P0 - 2 + j;
            int v = -1;
            if ((unsigned)p < (unsigned)SEQ) {
                int t = tok[b * SEQ + p];
                if (t >= 768) v = min(t - 768, 5);
            }
            stok[j] = v;
        }
        __syncthreads();
        // d1 conv into smem: PN pos x 16 ch
        for (int t = tid; t < PN * 4; t += 256) {
            int i = t >> 2, o4 = t & 3;
            int p = P0 + i;
            float4 acc = make_float4(0.f, 0.f, 0.f, 0.f);
            if ((unsigned)p < 4097u) {
                acc = __ldg(reinterpret_cast<const float4*>(d1b) + o4);
                #pragma unroll
                for (int k = 0; k < 4; k++) {
                    int v = stok[i + k];
                    if (v >= 0) {
                        float4 w = *reinterpret_cast<const float4*>(&g_wT_d[k][v][o4 * 4]);
                        acc.x += w.x; acc.y += w.y; acc.z += w.z; acc.w += w.w;
                    }
                }
                acc.x = fmaxf(acc.x, 0.f); acc.y = fmaxf(acc.y, 0.f);
                acc.z = fmaxf(acc.z, 0.f); acc.w = fmaxf(acc.w, 0.f);
            }
            *reinterpret_cast<float4*>(&s_x[(i * 4 + o4) * 4]) = acc;
        }
        __syncthreads();
        // d2 conv + adaptive pool: 4 sub-bins x (16 o x 4 j)
        const int qsub = tid >> 6, r = tid & 63;
        const int o = r >> 2, j = r & 3;
        const int q = q0 + qsub;
        const int s0 = (q * 4097) >> 7;
        const int e0 = ((q + 1) * 4097 + 127) >> 7;
        const float bo = __ldg(d2b + o);
        float sum = 0.f;
        for (int l = s0 + j; l < e0; l += 4) {
            ull a2 = 0;
            #pragma unroll
            for (int k = 0; k < 3; k++) {
                int i = l - 1 + k - P0;
                const ull* xr = reinterpret_cast<const ull*>(&s_x[i * 16]);
                const ull* wr = reinterpret_cast<const ull*>(&g_w2_d[o][k][0]);
                #pragma unroll
                for (int c2 = 0; c2 < 8; c2++)
                    fma2(a2, __ldg(wr + c2), xr[c2]);
            }
            float2 f = upk(a2);
            sum += fmaxf(f.x + f.y + bo, 0.f);
        }
        sum += __shfl_down_sync(0xffffffffu, sum, 2);
        sum += __shfl_down_sync(0xffffffffu, sum, 1);
        if (j == 0) g_dpool[b][q][o] = sum / (float)(e0 - s0);
    }
}

// ---------------- second-stage pooling + FC ----------------
__global__ void __launch_bounds__(256) final_kernel(const float* __restrict__ fcw,
                                                    const float* __restrict__ fcb) {
    __shared__ float comb[512];
    int b = blockIdx.x, tid = threadIdx.x;
    for (int idx = tid; idx < 512; idx += 256) {
        float v;
        if (idx < 128) {                       // rhythm
            int o = idx >> 1, hf = idx & 1; float s = 0.f;
            #pragma unroll
            for (int c = 0; c < 8; c++) s += g_part_r[b][hf * 8 + c][o];
            v = s * (1.f / 512.f);
        } else if (idx < 256) {                // harmony
            int i = idx - 128; int o = i >> 2, qk = i & 3; float s = 0.f;
            #pragma unroll
            for (int c = 0; c < 8; c++) s += g_part_h[b][qk * 8 + c][o];
            v = s * (1.f / 512.f);
        } else if (idx < 384) {                // melody
            int i = idx - 256; int o = i >> 2, qk = i & 3; float s = 0.f;
            #pragma unroll
            for (int c = 0; c < 8; c++) s += g_part_m[b][qk * 8 + c][o];
            v = s * (1.f / 1024.f);
        } else {                               // dynamics
            int i = idx - 384; int o = i >> 3, pk = i & 7; float s = 0.f;
            #pragma unroll
            for (int c = 0; c < 16; c++) s += g_dpool[b][pk * 16 + c][o];
            v = s * (1.f / 16.f);
        }
        comb[idx] = v;
    }
    __syncthreads();
    const float4* cw = reinterpret_cast<const float4*>(comb);
    for (int j = tid; j < 512; j += 256) {
        float acc = __ldg(fcb + j);
        const float4* wr = reinterpret_cast<const float4*>(fcw + (size_t)j * 512);
        #pragma unroll 4
        for (int i4 = 0; i4 < 128; i4++) {
            float4 w = __ldg(wr + i4);
            float4 c = cw[i4];
            acc = fmaf(w.x, c.x, acc);
            acc = fmaf(w.y, c.y, acc);
            acc = fmaf(w.z, c.z, acc);
            acc = fmaf(w.w, c.w, acc);
        }
        g_feats[b][j] = acc;
    }
}

// ---------------- broadcast feats -> out[b][s][512] ----------------
__global__ void __launch_bounds__(256) broadcast_kernel(float4* __restrict__ out) {
    const float4* f = reinterpret_cast<const float4*>(&g_feats[0][0]);
    const long long total = (long long)BATCH * SEQ * 128;
    long long stride = (long long)gridDim.x * blockDim.x;
    for (long long idx = (long long)blockIdx.x * blockDim.x + threadIdx.x; idx < total; idx += stride) {
        int j4 = (int)(idx & 127);
        int b  = (int)(idx >> 19);
        float4 v = __ldg(f + b * 128 + j4);
        __stcs(out + idx, v);
    }
}

// ---------------- launch ----------------
extern "C" void kernel_launch(void* const* d_in, const int* in_sizes, int n_in,
                              void* d_out, int out_size) {
    const int*   tok = (const int*)d_in[0];
    const float* r1w = (const float*)d_in[1];
    const float* r1b = (const float*)d_in[2];
    const float* r2w = (const float*)d_in[3];
    const float* r2b = (const float*)d_in[4];
    const float* h1w = (const float*)d_in[5];
    const float* h1b = (const float*)d_in[6];
    const float* h2w = (const float*)d_in[7];
    const float* h2b = (const float*)d_in[8];
    const float* m1w = (const float*)d_in[9];
    const float* m1b = (const float*)d_in[10];
    const float* m2w = (const float*)d_in[11];
    const float* m2b = (const float*)d_in[12];
    const float* d1w = (const float*)d_in[13];
    const float* d1b = (const float*)d_in[14];
    const float* d2w = (const float*)d_in[15];
    const float* d2b = (const float*)d_in[16];
    const float* fcw = (const float*)d_in[17];
    const float* fcb = (const float*)d_in[18];

    prep_kernel<<<96, 256>>>(r1w, r2w, h1w, h2w, m1w, m2w, d1w, d2w);
    branches_kernel<<<3584, 256>>>(tok, r1b, r2b, h1b, h2b, m1b, m2b, d1b, d2b);
    final_kernel<<<BATCH, 256>>>(fcw, fcb);
    broadcast_kernel<<<8192, 256>>>((float4*)d_out);
}

// round 11
// speedup vs baseline: 1.0006x; 1.0006x over previous
#include <cuda_runtime.h>

#define BATCH 32
#define SEQ   4096

typedef unsigned long long ull;

// ---------------- packed f32x2 helpers ----------------
__device__ __forceinline__ void fma2(ull& d, ull a, ull b) {
    asm("fma.rn.f32x2 %0, %1, %2, %0;" : "+l"(d) : "l"(a), "l"(b));
}
__device__ __forceinline__ float2 upk(ull v) {
    float2 f;
    asm("mov.b64 {%0, %1}, %2;" : "=f"(f.x), "=f"(f.y) : "l"(v));
    return f;
}

// ---------------- device scratch (no allocation) ----------------
// transposed first-layer weights: [k][token][o]
__device__ __align__(16) float g_wT_h[12][128][64];
__device__ __align__(16) float g_wT_m[5][128][64];
__device__ __align__(16) float g_wT_d[4][6][16];
__device__ __align__(16) float g_wT_r[8][32];

// transposed second-layer weights: [o][k][c]
__device__ __align__(16) float g_w2_h[32][8][64];
__device__ __align__(16) float g_w2_m[32][3][64];
__device__ __align__(16) float g_w2_r[64][4][32];
__device__ __align__(16) float g_w2_d[16][3][16];

// pooled partials
__device__ float g_part_r[BATCH][16][64];   // 16 chunks of 64 out-l
__device__ float g_part_h[BATCH][32][32];   // 32 chunks of 64 out-l
__device__ float g_part_m[BATCH][32][32];   // 32 chunks of 128 out-l
__device__ float g_dpool [BATCH][128][16];
__device__ __align__(16) float g_feats[BATCH][512];

// ---------------- weight prep (tiny) ----------------
__global__ void prep_kernel(const float* __restrict__ r1w, const float* __restrict__ r2w,
                            const float* __restrict__ h1w, const float* __restrict__ h2w,
                            const float* __restrict__ m1w, const float* __restrict__ m2w,
                            const float* __restrict__ d1w, const float* __restrict__ d2w) {
    int stride = gridDim.x * blockDim.x;
    int tid = blockIdx.x * blockDim.x + threadIdx.x;
    for (int i = tid; i < 64*128*12; i += stride) {
        int o = i / (128*12), r = i % (128*12), t = r / 12, k = r % 12;
        g_wT_h[k][t][o] = h1w[i];
    }
    for (int i = tid; i < 64*128*5; i += stride) {
        int o = i / 640, r = i % 640, t = r / 5, k = r % 5;
        g_wT_m[k][t][o] = m1w[i];
    }
    for (int i = tid; i < 16*6*4; i += stride) {
        int o = i / 24, r = i % 24, v = r / 4, k = r % 4;
        g_wT_d[k][v][o] = d1w[i];
    }
    for (int i = tid; i < 32*8; i += stride) {
        int o = i / 8, k = i % 8;
        g_wT_r[k][o] = r1w[i];
    }
    for (int i = tid; i < 32*64*8; i += stride) {
        int o = i / 512, r = i % 512, c = r / 8, k = r % 8;
        g_w2_h[o][k][c] = h2w[i];
    }
    for (int i = tid; i < 32*64*3; i += stride) {
        int o = i / 192, r = i % 192, c = r / 3, k = r % 3;
        g_w2_m[o][k][c] = m2w[i];
    }
    for (int i = tid; i < 64*32*4; i += stride) {
        int o = i / 128, r = i % 128, c = r / 4, k = r % 4;
        g_w2_r[o][k][c] = r2w[i];
    }
    for (int i = tid; i < 16*16*3; i += stride) {
        int o = i / 48, r = i % 48, c = r / 3, k = r % 3;
        g_w2_d[o][k][c] = d2w[i];
    }
}

// ---------------- fused branch mega-kernel ----------------
// blocks [0,1024): harmony   (b, chunk of 64 out-l;  32 chunks)
// blocks [1024,2048): melody (b, chunk of 128 out-l; 32 chunks)
// blocks [2048,2560): rhythm (b, chunk of 64 out-l;  16 chunks)
// blocks [2560,3584): dynamics (b, group of 4 q-bins; 32 groups)
__global__ void __launch_bounds__(256) branches_kernel(
    const int* __restrict__ tok,
    const float* __restrict__ r1b, const float* __restrict__ r2b,
    const float* __restrict__ h1b, const float* __restrict__ h2b,
    const float* __restrict__ m1b, const float* __restrict__ m2b,
    const float* __restrict__ d1b, const float* __restrict__ d2b)
{
    __shared__ __align__(16) float s_x[8576];   // conv1 tile, [pos][C]
    __shared__ __align__(16) float s_aux[272];  // tokens / ts window
    const int tid = threadIdx.x;
    const int bid = blockIdx.x;
    const int lane = tid & 31;
    const int wrp  = tid >> 5;

    if (bid < 1024) {
        // ================= HARMONY =================
        const int b = bid >> 5, chunk = bid & 31;
        const int L0 = chunk * 64;
        const int P0 = 2 * L0 - 3;          // conv1 pos base, 134 positions
        int* stok = (int*)s_aux;
        for (int j = tid; j < 145; j += 256) {
            int p = P0 - 6 + j;
            stok[j] = ((unsigned)p < (unsigned)SEQ) ? tok[b * SEQ + p] : -1;
        }
        __syncthreads();
        // conv1 into smem: 134 pos x 64 ch
        for (int t = tid; t < 134 * 16; t += 256) {
            int i = t >> 4, o4 = t & 15;
            int p = P0 + i;
            float4 acc = make_float4(0.f, 0.f, 0.f, 0.f);
            if ((unsigned)p < 4097u) {
                acc = __ldg(reinterpret_cast<const float4*>(h1b) + o4);
                #pragma unroll
                for (int k = 0; k < 12; k++) {
                    int tkn = stok[i + k];
                    if ((unsigned)tkn < 128u) {
                        float4 w = *reinterpret_cast<const float4*>(&g_wT_h[k][tkn][o4 * 4]);
                        acc.x += w.x; acc.y += w.y; acc.z += w.z; acc.w += w.w;
                    }
                }
                acc.x = fmaxf(acc.x, 0.f); acc.y = fmaxf(acc.y, 0.f);
                acc.z = fmaxf(acc.z, 0.f); acc.w = fmaxf(acc.w, 0.f);
            }
            *reinterpret_cast<float4*>(&s_x[(i * 16 + o4) * 4]) = acc;
        }
        __syncthreads();
        // conv2: lane -> 2 l, warp -> 4 o. i = 4*lane + 2d + k.
        const int ob = wrp * 4;
        const int ib = 4 * lane;
        ull acc[4][2] = {{0,0},{0,0},{0,0},{0,0}};
        #pragma unroll
        for (int c4 = 0; c4 < 16; c4++) {
            ulonglong2 in[10];
            #pragma unroll
            for (int r = 0; r < 10; r++)
                in[r] = *reinterpret_cast<const ulonglong2*>(&s_x[((ib + r) * 16 + c4) * 4]);
            #pragma unroll
            for (int k = 0; k < 8; k++) {
                #pragma unroll
                for (int o = 0; o < 4; o++) {
                    ulonglong2 ww = __ldg(reinterpret_cast<const ulonglong2*>(&g_w2_h[ob + o][k][c4 * 4]));
                    fma2(acc[o][0], ww.x, in[k].x);
                    fma2(acc[o][0], ww.y, in[k].y);
                    fma2(acc[o][1], ww.x, in[k + 2].x);
                    fma2(acc[o][1], ww.y, in[k + 2].y);
                }
            }
        }
        #pragma unroll
        for (int o = 0; o < 4; o++) {
            float bo = __ldg(h2b + ob + o);
            float2 f0 = upk(acc[o][0]), f1 = upk(acc[o][1]);
            float s = fmaxf(f0.x + f0.y + bo, 0.f) + fmaxf(f1.x + f1.y + bo, 0.f);
            #pragma unroll
            for (int off = 16; off > 0; off >>= 1)
                s += __shfl_down_sync(0xffffffffu, s, off);
            if (lane == 0) g_part_h[b][chunk][ob + o] = s;
        }
    } else if (bid < 2048) {
        // ================= MELODY =================
        const int idx = bid - 1024;
        const int b = idx >> 5, chunk = idx & 31;
        const int L0 = chunk * 128;
        const int P0 = L0 - 1;              // 130 positions
        int* stok = (int*)s_aux;
        for (int j = tid; j < 134; j += 256) {
            int p = P0 - 2 + j;
            stok[j] = ((unsigned)p < (unsigned)SEQ) ? tok[b * SEQ + p] : -1;
        }
        __syncthreads();
        for (int t = tid; t < 130 * 16; t += 256) {
            int i = t >> 4, o4 = t & 15;
            int p = P0 + i;
            float4 acc = make_float4(0.f, 0.f, 0.f, 0.f);
            if ((unsigned)p < 4096u) {
                acc = __ldg(reinterpret_cast<const float4*>(m1b) + o4);
                #pragma unroll
                for (int k = 0; k < 5; k++) {
                    int tkn = stok[i + k];
                    if ((unsigned)tkn < 128u) {
                        float4 w = *reinterpret_cast<const float4*>(&g_wT_m[k][tkn][o4 * 4]);
                        acc.x += w.x; acc.y += w.y; acc.z += w.z; acc.w += w.w;
                    }
                }
                acc.x = fmaxf(acc.x, 0.f); acc.y = fmaxf(acc.y, 0.f);
                acc.z = fmaxf(acc.z, 0.f); acc.w = fmaxf(acc.w, 0.f);
            }
            *reinterpret_cast<float4*>(&s_x[(i * 16 + o4) * 4]) = acc;
        }
        __syncthreads();
        // conv2: lane -> 4 l, warp -> 4 o. i = 4*lane + d + k.
        const int ob = wrp * 4;
        const int ib = 4 * lane;
        ull acc[4][4] = {};
        #pragma unroll
        for (int c4 = 0; c4 < 16; c4++) {
            ulonglong2 in[7];
            #pragma unroll
            for (int r = 0; r < 7; r++)
                in[r] = *reinterpret_cast<const ulonglong2*>(&s_x[((ib + r) * 16 + c4) * 4]);
            #pragma unroll
            for (int k = 0; k < 3; k++) {
                #pragma unroll
                for (int o = 0; o < 4; o++) {
                    ulonglong2 ww = __ldg(reinterpret_cast<const ulonglong2*>(&g_w2_m[ob + o][k][c4 * 4]));
                    #pragma unroll
                    for (int d = 0; d < 4; d++) {
                        fma2(acc[o][d], ww.x, in[k + d].x);
                        fma2(acc[o][d], ww.y, in[k + d].y);
                    }
                }
            }
        }
        #pragma unroll
        for (int o = 0; o < 4; o++) {
            float bo = __ldg(m2b + ob + o);
            float s = 0.f;
            #pragma unroll
            for (int d = 0; d < 4; d++) {
                float2 f = upk(acc[o][d]);
                s += fmaxf(f.x + f.y + bo, 0.f);
            }
            #pragma unroll
            for (int off = 16; off > 0; off >>= 1)
                s += __shfl_down_sync(0xffffffffu, s, off);
            if (lane == 0) g_part_m[b][chunk][ob + o] = s;
        }
    } else if (bid < 2560) {
        // ================= RHYTHM =================
        const int idx = bid - 2048;
        const int b = idx >> 4, chunk = idx & 15;
        const int L0 = chunk * 64;
        const int P0 = 2 * L0 - 1;          // 131 r1 positions
        const int T0 = 2 * P0 - 3;          // ts window base, 268 values
        for (int j = tid; j < 268; j += 256) {
            int tp = T0 + j;
            float v = 0.f;
            if ((unsigned)tp < (unsigned)SEQ) {
                int t = tok[b * SEQ + tp];
                v = (t >= 256 && t < 768) ? 1.f : 0.f;
            }
            s_aux[j] = v;
        }
        __syncthreads();
        // r1 conv into smem: 131 pos x 32 ch
        for (int t = tid; t < 131 * 8; t += 256) {
            int i = t >> 3, o4 = t & 7;
            int p = P0 + i;
            float4 acc = make_float4(0.f, 0.f, 0.f, 0.f);
            if ((unsigned)p < 2048u) {
                acc = __ldg(reinterpret_cast<const float4*>(r1b) + o4);
                #pragma unroll
                for (int k = 0; k < 8; k++) {
                    float tv = s_aux[2 * i + k];
                    float4 w = *reinterpret_cast<const float4*>(&g_wT_r[k][o4 * 4]);
                    acc.x = fmaf(tv, w.x, acc.x);
                    acc.y = fmaf(tv, w.y, acc.y);
                    acc.z = fmaf(tv, w.z, acc.z);
                    acc.w = fmaf(tv, w.w, acc.w);
                }
                acc.x = fmaxf(acc.x, 0.f); acc.y = fmaxf(acc.y, 0.f);
                acc.z = fmaxf(acc.z, 0.f); acc.w = fmaxf(acc.w, 0.f);
            }
            *reinterpret_cast<float4*>(&s_x[(i * 8 + o4) * 4]) = acc;
        }
        __syncthreads();
        // conv2: lane -> 2 l, warp -> 8 o. i = 4*lane + 2d + k, k in [0,4).
        const int ob = wrp * 8;
        const int ib = 4 * lane;
        ull acc[8][2] = {};
        #pragma unroll
        for (int c4 = 0; c4 < 8; c4++) {
            ulonglong2 in[6];
            #pragma unroll
            for (int r = 0; r < 6; r++)
                in[r] = *reinterpret_cast<const ulonglong2*>(&s_x[((ib + r) * 8 + c4) * 4]);
            #pragma unroll
            for (int k = 0; k < 4; k++) {
                #pragma unroll
                for (int o = 0; o < 8; o++) {
                    ulonglong2 ww = __ldg(reinterpret_cast<const ulonglong2*>(&g_w2_r[ob + o][k][c4 * 4]));
                    fma2(acc[o][0], ww.x, in[k].x);
                    fma2(acc[o][0], ww.y, in[k].y);
                    fma2(acc[o][1], ww.x, in[k + 2].x);
                    fma2(acc[o][1], ww.y, in[k + 2].y);
                }
            }
        }
        #pragma unroll
        for (int o = 0; o < 8; o++) {
            float bo = __ldg(r2b + ob + o);
            float2 f0 = upk(acc[o][0]), f1 = upk(acc[o][1]);
            float s = fmaxf(f0.x + f0.y + bo, 0.f) + fmaxf(f1.x + f1.y + bo, 0.f);
            #pragma unroll
            for (int off = 16; off > 0; off >>= 1)
                s += __shfl_down_sync(0xffffffffu, s, off);
            if (lane == 0) g_part_r[b][chunk][ob + o] = s;
        }
    } else {
        // ================= DYNAMICS =================
        const int idx = bid - 2560;
        const int b = idx >> 5, qg = idx & 31;
        const int q0 = qg * 4;
        const int s_all = (q0 * 4097) >> 7;
        const int e_all = ((q0 + 4) * 4097 + 127) >> 7;
        const int P0 = s_all - 1;
        const int PN = e_all - s_all + 2;   // <= 131
        int* stok = (int*)s_aux;
        for (int j = tid; j < PN + 3; j += 256) {
            int p = P0 - 2 + j;
            int v = -1;
            if ((unsigned)p < (unsigned)SEQ) {
                int t = tok[b * SEQ + p];
                if (t >= 768) v = min(t - 768, 5);
            }
            stok[j] = v;
        }
        __syncthreads();
        // d1 conv into smem: PN pos x 16 ch
        for (int t = tid; t < PN * 4; t += 256) {
            int i = t >> 2, o4 = t & 3;
            int p = P0 + i;
            float4 acc = make_float4(0.f, 0.f, 0.f, 0.f);
            if ((unsigned)p < 4097u) {
                acc = __ldg(reinterpret_cast<const float4*>(d1b) + o4);
                #pragma unroll
                for (int k = 0; k < 4; k++) {
                    int v = stok[i + k];
                    if (v >= 0) {
                        float4 w = *reinterpret_cast<const float4*>(&g_wT_d[k][v][o4 * 4]);
                        acc.x += w.x; acc.y += w.y; acc.z += w.z; acc.w += w.w;
                    }
                }
                acc.x = fmaxf(acc.x, 0.f); acc.y = fmaxf(acc.y, 0.f);
                acc.z = fmaxf(acc.z, 0.f); acc.w = fmaxf(acc.w, 0.f);
            }
            *reinterpret_cast<float4*>(&s_x[(i * 4 + o4) * 4]) = acc;
        }
        __syncthreads();
        // d2 conv + adaptive pool: 4 sub-bins x (16 o x 4 j)
        const int qsub = tid >> 6, r = tid & 63;
        const int o = r >> 2, j = r & 3;
        const int q = q0 + qsub;
        const int s0 = (q * 4097) >> 7;
        const int e0 = ((q + 1) * 4097 + 127) >> 7;
        const float bo = __ldg(d2b + o);
        float sum = 0.f;
        for (int l = s0 + j; l < e0; l += 4) {
            ull a2 = 0;
            #pragma unroll
            for (int k = 0; k < 3; k++) {
                int i = l - 1 + k - P0;
                const ull* xr = reinterpret_cast<const ull*>(&s_x[i * 16]);
                const ull* wr = reinterpret_cast<const ull*>(&g_w2_d[o][k][0]);
                #pragma unroll
                for (int c2 = 0; c2 < 8; c2++)
                    fma2(a2, __ldg(wr + c2), xr[c2]);
            }
            float2 f = upk(a2);
            sum += fmaxf(f.x + f.y + bo, 0.f);
        }
        sum += __shfl_down_sync(0xffffffffu, sum, 2);
        sum += __shfl_down_sync(0xffffffffu, sum, 1);
        if (j == 0) g_dpool[b][q][o] = sum / (float)(e0 - s0);
    }
}

// ---------------- second-stage pooling + FC ----------------
__global__ void __launch_bounds__(256) final_kernel(const float* __restrict__ fcw,
                                                    const float* __restrict__ fcb) {
    __shared__ float comb[512];
    int b = blockIdx.x, tid = threadIdx.x;
    for (int idx = tid; idx < 512; idx += 256) {
        float v;
        if (idx < 128) {                       // rhythm
            int o = idx >> 1, hf = idx & 1; float s = 0.f;
            #pragma unroll
            for (int c = 0; c < 8; c++) s += g_part_r[b][hf * 8 + c][o];
            v = s * (1.f / 512.f);
        } else if (idx < 256) {                // harmony
            int i = idx - 128; int o = i >> 2, qk = i & 3; float s = 0.f;
            #pragma unroll
            for (int c = 0; c < 8; c++) s += g_part_h[b][qk * 8 + c][o];
            v = s * (1.f / 512.f);
        } else if (idx < 384) {                // melody
            int i = idx - 256; int o = i >> 2, qk = i & 3; float s = 0.f;
            #pragma unroll
            for (int c = 0; c < 8; c++) s += g_part_m[b][qk * 8 + c][o];
            v = s * (1.f / 1024.f);
        } else {                               // dynamics
            int i = idx - 384; int o = i >> 3, pk = i & 7; float s = 0.f;
            #pragma unroll
            for (int c = 0; c < 16; c++) s += g_dpool[b][pk * 16 + c][o];
            v = s * (1.f / 16.f);
        }
        comb[idx] = v;
    }
    __syncthreads();
    const float4* cw = reinterpret_cast<const float4*>(comb);
    for (int j = tid; j < 512; j += 256) {
        float acc = __ldg(fcb + j);
        const float4* wr = reinterpret_cast<const float4*>(fcw + (size_t)j * 512);
        #pragma unroll 4
        for (int i4 = 0; i4 < 128; i4++) {
            float4 w = __ldg(wr + i4);
            float4 c = cw[i4];
            acc = fmaf(w.x, c.x, acc);
            acc = fmaf(w.y, c.y, acc);
            acc = fmaf(w.z, c.z, acc);
            acc = fmaf(w.w, c.w, acc);
        }
        g_feats[b][j] = acc;
    }
}

// ---------------- broadcast feats -> out[b][s][512] ----------------
__global__ void __launch_bounds__(256) broadcast_kernel(float4* __restrict__ out) {
    const float4* f = reinterpret_cast<const float4*>(&g_feats[0][0]);
    const long long total = (long long)BATCH * SEQ * 128;
    long long stride = (long long)gridDim.x * blockDim.x;
    for (long long idx = (long long)blockIdx.x * blockDim.x + threadIdx.x; idx < total; idx += stride) {
        int j4 = (int)(idx & 127);
        int b  = (int)(idx >> 19);
        float4 v = __ldg(f + b * 128 + j4);
        __stcs(out + idx, v);
    }
}

// ---------------- launch ----------------
extern "C" void kernel_launch(void* const* d_in, const int* in_sizes, int n_in,
                              void* d_out, int out_size) {
    const int*   tok = (const int*)d_in[0];
    const float* r1w = (const float*)d_in[1];
    const float* r1b = (const float*)d_in[2];
    const float* r2w = (const float*)d_in[3];
    const float* r2b = (const float*)d_in[4];
    const float* h1w = (const float*)d_in[5];
    const float* h1b = (const float*)d_in[6];
    const float* h2w = (const float*)d_in[7];
    const float* h2b = (const float*)d_in[8];
    const float* m1w = (const float*)d_in[9];
    const float* m1b = (const float*)d_in[10];
    const float* m2w = (const float*)d_in[11];
    const float* m2b = (const float*)d_in[12];
    const float* d1w = (const float*)d_in[13];
    const float* d1b = (const float*)d_in[14];
    const float* d2w = (const float*)d_in[15];
    const float* d2b = (const float*)d_in[16];
    const float* fcw = (const float*)d_in[17];
    const float* fcb = (const float*)d_in[18];

    prep_kernel<<<96, 256>>>(r1w, r2w, h1w, h2w, m1w, m2w, d1w, d2w);
    branches_kernel<<<3584, 256>>>(tok, r1b, r2b, h1b, h2b, m1b, m2b, d1b, d2b);
    final_kernel<<<BATCH, 256>>>(fcw, fcb);
    broadcast_kernel<<<8192, 256>>>((float4*)d_out);
}

// round 12
// speedup vs baseline: 1.0008x; 1.0003x over previous
#include <cuda_runtime.h>

#define BATCH 32
#define SEQ   4096

typedef unsigned long long ull;

// ---------------- packed f32x2 helpers ----------------
__device__ __forceinline__ void fma2(ull& d, ull a, ull b) {
    asm("fma.rn.f32x2 %0, %1, %2, %0;" : "+l"(d) : "l"(a), "l"(b));
}
__device__ __forceinline__ float2 upk(ull v) {
    float2 f;
    asm("mov.b64 {%0, %1}, %2;" : "=f"(f.x), "=f"(f.y) : "l"(v));
    return f;
}

// ---------------- device scratch (no allocation) ----------------
// transposed first-layer weights: [k][token][o]
__device__ __align__(16) float g_wT_h[12][128][64];
__device__ __align__(16) float g_wT_m[5][128][64];
__device__ __align__(16) float g_wT_d[4][6][16];
__device__ __align__(16) float g_wT_r[8][32];

// transposed second-layer weights: [o][k][c]
__device__ __align__(16) float g_w2_h[32][8][64];
__device__ __align__(16) float g_w2_m[32][3][64];
__device__ __align__(16) float g_w2_r[64][4][32];
__device__ __align__(16) float g_w2_d[16][3][16];

// pooled partials
__device__ float g_part_r[BATCH][16][64];   // 16 chunks of 64 out-l
__device__ float g_part_h[BATCH][32][32];   // 32 chunks of 64 out-l
__device__ float g_part_m[BATCH][32][32];   // 32 chunks of 128 out-l
__device__ float g_dpool [BATCH][128][16];
__device__ __align__(16) float g_feats[BATCH][512];

// ---------------- weight prep (tiny) ----------------
__global__ void prep_kernel(const float* __restrict__ r1w, const float* __restrict__ r2w,
                            const float* __restrict__ h1w, const float* __restrict__ h2w,
                            const float* __restrict__ m1w, const float* __restrict__ m2w,
                            const float* __restrict__ d1w, const float* __restrict__ d2w) {
    int stride = gridDim.x * blockDim.x;
    int tid = blockIdx.x * blockDim.x + threadIdx.x;
    for (int i = tid; i < 64*128*12; i += stride) {
        int o = i / (128*12), r = i % (128*12), t = r / 12, k = r % 12;
        g_wT_h[k][t][o] = h1w[i];
    }
    for (int i = tid; i < 64*128*5; i += stride) {
        int o = i / 640, r = i % 640, t = r / 5, k = r % 5;
        g_wT_m[k][t][o] = m1w[i];
    }
    for (int i = tid; i < 16*6*4; i += stride) {
        int o = i / 24, r = i % 24, v = r / 4, k = r % 4;
        g_wT_d[k][v][o] = d1w[i];
    }
    for (int i = tid; i < 32*8; i += stride) {
        int o = i / 8, k = i % 8;
        g_wT_r[k][o] = r1w[i];
    }
    for (int i = tid; i < 32*64*8; i += stride) {
        int o = i / 512, r = i % 512, c = r / 8, k = r % 8;
        g_w2_h[o][k][c] = h2w[i];
    }
    for (int i = tid; i < 32*64*3; i += stride) {
        int o = i / 192, r = i % 192, c = r / 3, k = r % 3;
        g_w2_m[o][k][c] = m2w[i];
    }
    for (int i = tid; i < 64*32*4; i += stride) {
        int o = i / 128, r = i % 128, c = r / 4, k = r % 4;
        g_w2_r[o][k][c] = r2w[i];
    }
    for (int i = tid; i < 16*16*3; i += stride) {
        int o = i / 48, r = i % 48, c = r / 3, k = r % 3;
        g_w2_d[o][k][c] = d2w[i];
    }
}

// ---------------- fused branch mega-kernel ----------------
// blocks [0,1024): harmony   (b, chunk of 64 out-l;  32 chunks)
// blocks [1024,2048): melody (b, chunk of 128 out-l; 32 chunks)
// blocks [2048,2560): rhythm (b, chunk of 64 out-l;  16 chunks)
// blocks [2560,3584): dynamics (b, group of 4 q-bins; 32 groups)
__global__ void __launch_bounds__(256) branches_kernel(
    const int* __restrict__ tok,
    const float* __restrict__ r1b, const float* __restrict__ r2b,
    const float* __restrict__ h1b, const float* __restrict__ h2b,
    const float* __restrict__ m1b, const float* __restrict__ m2b,
    const float* __restrict__ d1b, const float* __restrict__ d2b)
{
    __shared__ __align__(16) float s_x[8576];   // conv1 tile, [pos][C]
    __shared__ __align__(16) float s_aux[272];  // tokens / ts window
    const int tid = threadIdx.x;
    const int bid = blockIdx.x;
    const int lane = tid & 31;
    const int wrp  = tid >> 5;

    if (bid < 1024) {
        // ================= HARMONY =================
        const int b = bid >> 5, chunk = bid & 31;
        const int L0 = chunk * 64;
        const int P0 = 2 * L0 - 3;          // conv1 pos base, 134 positions
        int* stok = (int*)s_aux;
        for (int j = tid; j < 145; j += 256) {
            int p = P0 - 6 + j;
            stok[j] = ((unsigned)p < (unsigned)SEQ) ? tok[b * SEQ + p] : -1;
        }
        __syncthreads();
        // conv1 into smem: 134 pos x 64 ch
        for (int t = tid; t < 134 * 16; t += 256) {
            int i = t >> 4, o4 = t & 15;
            int p = P0 + i;
            float4 acc = make_float4(0.f, 0.f, 0.f, 0.f);
            if ((unsigned)p < 4097u) {
                acc = __ldg(reinterpret_cast<const float4*>(h1b) + o4);
                #pragma unroll
                for (int k = 0; k < 12; k++) {
                    int tkn = stok[i + k];
                    if ((unsigned)tkn < 128u) {
                        float4 w = *reinterpret_cast<const float4*>(&g_wT_h[k][tkn][o4 * 4]);
                        acc.x += w.x; acc.y += w.y; acc.z += w.z; acc.w += w.w;
                    }
                }
                acc.x = fmaxf(acc.x, 0.f); acc.y = fmaxf(acc.y, 0.f);
                acc.z = fmaxf(acc.z, 0.f); acc.w = fmaxf(acc.w, 0.f);
            }
            *reinterpret_cast<float4*>(&s_x[(i * 16 + o4) * 4]) = acc;
        }
        __syncthreads();
        // conv2: lane -> 2 l, warp -> 4 o. i = 4*lane + 2d + k.
        const int ob = wrp * 4;
        const int ib = 4 * lane;
        ull acc[4][2] = {{0,0},{0,0},{0,0},{0,0}};
        #pragma unroll
        for (int c4 = 0; c4 < 16; c4++) {
            ulonglong2 in[10];
            #pragma unroll
            for (int r = 0; r < 10; r++)
                in[r] = *reinterpret_cast<const ulonglong2*>(&s_x[((ib + r) * 16 + c4) * 4]);
            #pragma unroll
            for (int k = 0; k < 8; k++) {
                #pragma unroll
                for (int o = 0; o < 4; o++) {
                    ulonglong2 ww = __ldg(reinterpret_cast<const ulonglong2*>(&g_w2_h[ob + o][k][c4 * 4]));
                    fma2(acc[o][0], ww.x, in[k].x);
                    fma2(acc[o][0], ww.y, in[k].y);
                    fma2(acc[o][1], ww.x, in[k + 2].x);
                    fma2(acc[o][1], ww.y, in[k + 2].y);
                }
            }
        }
        #pragma unroll
        for (int o = 0; o < 4; o++) {
            float bo = __ldg(h2b + ob + o);
            float2 f0 = upk(acc[o][0]), f1 = upk(acc[o][1]);
            float s = fmaxf(f0.x + f0.y + bo, 0.f) + fmaxf(f1.x + f1.y + bo, 0.f);
            #pragma unroll
            for (int off = 16; off > 0; off >>= 1)
                s += __shfl_down_sync(0xffffffffu, s, off);
            if (lane == 0) g_part_h[b][chunk][ob + o] = s;
        }
    } else if (bid < 2048) {
        // ================= MELODY =================
        const int idx = bid - 1024;
        const int b = idx >> 5, chunk = idx & 31;
        const int L0 = chunk * 128;
        const int P0 = L0 - 1;              // 130 positions
        int* stok = (int*)s_aux;
        for (int j = tid; j < 134; j += 256) {
            int p = P0 - 2 + j;
            stok[j] = ((unsigned)p < (unsigned)SEQ) ? tok[b * SEQ + p] : -1;
        }
        __syncthreads();
        for (int t = tid; t < 130 * 16; t += 256) {
            int i = t >> 4, o4 = t & 15;
            int p = P0 + i;
            float4 acc = make_float4(0.f, 0.f, 0.f, 0.f);
            if ((unsigned)p < 4096u) {
                acc = __ldg(reinterpret_cast<const float4*>(m1b) + o4);
                #pragma unroll
                for (int k = 0; k < 5; k++) {
                    int tkn = stok[i + k];
                    if ((unsigned)tkn < 128u) {
                        float4 w = *reinterpret_cast<const float4*>(&g_wT_m[k][tkn][o4 * 4]);
                        acc.x += w.x; acc.y += w.y; acc.z += w.z; acc.w += w.w;
                    }
                }
                acc.x = fmaxf(acc.x, 0.f); acc.y = fmaxf(acc.y, 0.f);
                acc.z = fmaxf(acc.z, 0.f); acc.w = fmaxf(acc.w, 0.f);
            }
            *reinterpret_cast<float4*>(&s_x[(i * 16 + o4) * 4]) = acc;
        }
        __syncthreads();
        // conv2: lane -> 4 l, warp -> 4 o. i = 4*lane + d + k.
        const int ob = wrp * 4;
        const int ib = 4 * lane;
        ull acc[4][4] = {};
        #pragma unroll
        for (int c4 = 0; c4 < 16; c4++) {
            ulonglong2 in[7];
            #pragma unroll
            for (int r = 0; r < 7; r++)
                in[r] = *reinterpret_cast<const ulonglong2*>(&s_x[((ib + r) * 16 + c4) * 4]);
            #pragma unroll
            for (int k = 0; k < 3; k++) {
                #pragma unroll
                for (int o = 0; o < 4; o++) {
                    ulonglong2 ww = __ldg(reinterpret_cast<const ulonglong2*>(&g_w2_m[ob + o][k][c4 * 4]));
                    #pragma unroll
                    for (int d = 0; d < 4; d++) {
                        fma2(acc[o][d], ww.x, in[k + d].x);
                        fma2(acc[o][d], ww.y, in[k + d].y);
                    }
                }
            }
        }
        #pragma unroll
        for (int o = 0; o < 4; o++) {
            float bo = __ldg(m2b + ob + o);
            float s = 0.f;
            #pragma unroll
            for (int d = 0; d < 4; d++) {
                float2 f = upk(acc[o][d]);
                s += fmaxf(f.x + f.y + bo, 0.f);
            }
            #pragma unroll
            for (int off = 16; off > 0; off >>= 1)
                s += __shfl_down_sync(0xffffffffu, s, off);
            if (lane == 0) g_part_m[b][chunk][ob + o] = s;
        }
    } else if (bid < 2560) {
        // ================= RHYTHM =================
        const int idx = bid - 2048;
        const int b = idx >> 4, chunk = idx & 15;
        const int L0 = chunk * 64;
        const int P0 = 2 * L0 - 1;          // 131 r1 positions
        const int T0 = 2 * P0 - 3;          // ts window base, 268 values
        for (int j = tid; j < 268; j += 256) {
            int tp = T0 + j;
            float v = 0.f;
            if ((unsigned)tp < (unsigned)SEQ) {
                int t = tok[b * SEQ + tp];
                v = (t >= 256 && t < 768) ? 1.f : 0.f;
            }
            s_aux[j] = v;
        }
        __syncthreads();
        // r1 conv into smem: 131 pos x 32 ch
        for (int t = tid; t < 131 * 8; t += 256) {
            int i = t >> 3, o4 = t & 7;
            int p = P0 + i;
            float4 acc = make_float4(0.f, 0.f, 0.f, 0.f);
            if ((unsigned)p < 2048u) {
                acc = __ldg(reinterpret_cast<const float4*>(r1b) + o4);
                #pragma unroll
                for (int k = 0; k < 8; k++) {
                    float tv = s_aux[2 * i + k];
                    float4 w = *reinterpret_cast<const float4*>(&g_wT_r[k][o4 * 4]);
                    acc.x = fmaf(tv, w.x, acc.x);
                    acc.y = fmaf(tv, w.y, acc.y);
                    acc.z = fmaf(tv, w.z, acc.z);
                    acc.w = fmaf(tv, w.w, acc.w);
                }
                acc.x = fmaxf(acc.x, 0.f); acc.y = fmaxf(acc.y, 0.f);
                acc.z = fmaxf(acc.z, 0.f); acc.w = fmaxf(acc.w, 0.f);
            }
            *reinterpret_cast<float4*>(&s_x[(i * 8 + o4) * 4]) = acc;
        }
        __syncthreads();
        // conv2: lane -> 2 l, warp -> 8 o. i = 4*lane + 2d + k, k in [0,4).
        const int ob = wrp * 8;
        const int ib = 4 * lane;
        ull acc[8][2] = {};
        #pragma unroll
        for (int c4 = 0; c4 < 8; c4++) {
            ulonglong2 in[6];
            #pragma unroll
            for (int r = 0; r < 6; r++)
                in[r] = *reinterpret_cast<const ulonglong2*>(&s_x[((ib + r) * 8 + c4) * 4]);
            #pragma unroll
            for (int k = 0; k < 4; k++) {
                #pragma unroll
                for (int o = 0; o < 8; o++) {
                    ulonglong2 ww = __ldg(reinterpret_cast<const ulonglong2*>(&g_w2_r[ob + o][k][c4 * 4]));
                    fma2(acc[o][0], ww.x, in[k].x);
                    fma2(acc[o][0], ww.y, in[k].y);
                    fma2(acc[o][1], ww.x, in[k + 2].x);
                    fma2(acc[o][1], ww.y, in[k + 2].y);
                }
            }
        }
        #pragma unroll
        for (int o = 0; o < 8; o++) {
            float bo = __ldg(r2b + ob + o);
            float2 f0 = upk(acc[o][0]), f1 = upk(acc[o][1]);
            float s = fmaxf(f0.x + f0.y + bo, 0.f) + fmaxf(f1.x + f1.y + bo, 0.f);
            #pragma unroll
            for (int off = 16; off > 0; off >>= 1)
                s += __shfl_down_sync(0xffffffffu, s, off);
            if (lane == 0) g_part_r[b][chunk][ob + o] = s;
        }
    } else {
        // ================= DYNAMICS =================
        const int idx = bid - 2560;
        const int b = idx >> 5, qg = idx & 31;
        const int q0 = qg * 4;
        const int s_all = (q0 * 4097) >> 7;
        const int e_all = ((q0 + 4) * 4097 + 127) >> 7;
        const int P0 = s_all - 1;
        const int PN = e_all - s_all + 2;   // <= 131
        int* stok = (int*)s_aux;
        for (int j = tid; j < PN + 3; j += 256) {
            int p = P0 - 2 + j;
            int v = -1;
            if ((unsigned)p < (unsigned)SEQ) {
                int t = tok[b * SEQ + p];
                if (t >= 768) v = min(t - 768, 5);
            }
            stok[j] = v;
        }
        __syncthreads();
        // d1 conv into smem: PN pos x 16 ch
        for (int t = tid; t < PN * 4; t += 256) {
            int i = t >> 2, o4 = t & 3;
            int p = P0 + i;
            float4 acc = make_float4(0.f, 0.f, 0.f, 0.f);
            if ((unsigned)p < 4097u) {
                acc = __ldg(reinterpret_cast<const float4*>(d1b) + o4);
                #pragma unroll
                for (int k = 0; k < 4; k++) {
                    int v = stok[i + k];
                    if (v >= 0) {
                        float4 w = *reinterpret_cast<const float4*>(&g_wT_d[k][v][o4 * 4]);
                        acc.x += w.x; acc.y += w.y; acc.z += w.z; acc.w += w.w;
                    }
                }
                acc.x = fmaxf(acc.x, 0.f); acc.y = fmaxf(acc.y, 0.f);
                acc.z = fmaxf(acc.z, 0.f); acc.w = fmaxf(acc.w, 0.f);
            }
            *reinterpret_cast<float4*>(&s_x[(i * 4 + o4) * 4]) = acc;
        }
        __syncthreads();
        // d2 conv + adaptive pool: 4 sub-bins x (16 o x 4 j)
        const int qsub = tid >> 6, r = tid & 63;
        const int o = r >> 2, j = r & 3;
        const int q = q0 + qsub;
        const int s0 = (q * 4097) >> 7;
        const int e0 = ((q + 1) * 4097 + 127) >> 7;
        const float bo = __ldg(d2b + o);
        float sum = 0.f;
        for (int l = s0 + j; l < e0; l += 4) {
            ull a2 = 0;
            #pragma unroll
            for (int k = 0; k < 3; k++) {
                int i = l - 1 + k - P0;
                const ull* xr = reinterpret_cast<const ull*>(&s_x[i * 16]);
                const ull* wr = reinterpret_cast<const ull*>(&g_w2_d[o][k][0]);
                #pragma unroll
                for (int c2 = 0; c2 < 8; c2++)
                    fma2(a2, __ldg(wr + c2), xr[c2]);
            }
            float2 f = upk(a2);
            sum += fmaxf(f.x + f.y + bo, 0.f);
        }
        sum += __shfl_down_sync(0xffffffffu, sum, 2);
        sum += __shfl_down_sync(0xffffffffu, sum, 1);
        if (j == 0) g_dpool[b][q][o] = sum / (float)(e0 - s0);
    }
}

// ---------------- second-stage pooling + FC ----------------
__global__ void __launch_bounds__(256) final_kernel(const float* __restrict__ fcw,
                                                    const float* __restrict__ fcb) {
    __shared__ float comb[512];
    int b = blockIdx.x, tid = threadIdx.x;
    for (int idx = tid; idx < 512; idx += 256) {
        float v;
        if (idx < 128) {                       // rhythm
            int o = idx >> 1, hf = idx & 1; float s = 0.f;
            #pragma unroll
            for (int c = 0; c < 8; c++) s += g_part_r[b][hf * 8 + c][o];
            v = s * (1.f / 512.f);
        } else if (idx < 256) {                // harmony
            int i = idx - 128; int o = i >> 2, qk = i & 3; float s = 0.f;
            #pragma unroll
            for (int c = 0; c < 8; c++) s += g_part_h[b][qk * 8 + c][o];
            v = s * (1.f / 512.f);
        } else if (idx < 384) {                // melody
            int i = idx - 256; int o = i >> 2, qk = i & 3; float s = 0.f;
            #pragma unroll
            for (int c = 0; c < 8; c++) s += g_part_m[b][qk * 8 + c][o];
            v = s * (1.f / 1024.f);
        } else {                               // dynamics
            int i = idx - 384; int o = i >> 3, pk = i & 7; float s = 0.f;
            #pragma unroll
            for (int c = 0; c < 16; c++) s += g_dpool[b][pk * 16 + c][o];
            v = s * (1.f / 16.f);
        }
        comb[idx] = v;
    }
    __syncthreads();
    const float4* cw = reinterpret_cast<const float4*>(comb);
    for (int j = tid; j < 512; j += 256) {
        float acc = __ldg(fcb + j);
        const float4* wr = reinterpret_cast<const float4*>(fcw + (size_t)j * 512);
        #pragma unroll 4
        for (int i4 = 0; i4 < 128; i4++) {
            float4 w = __ldg(wr + i4);
            float4 c = cw[i4];
            acc = fmaf(w.x, c.x, acc);
            acc = fmaf(w.y, c.y, acc);
            acc = fmaf(w.z, c.z, acc);
            acc = fmaf(w.w, c.w, acc);
        }
        g_feats[b][j] = acc;
    }
}

// ---------------- broadcast feats -> out[b][s][512] ----------------
__global__ void __launch_bounds__(256) broadcast_kernel(float4* __restrict__ out) {
    const float4* f = reinterpret_cast<const float4*>(&g_feats[0][0]);
    const long long total = (long long)BATCH * SEQ * 128;
    long long stride = (long long)gridDim.x * blockDim.x;
    for (long long idx = (long long)blockIdx.x * blockDim.x + threadIdx.x; idx < total; idx += stride) {
        int j4 = (int)(idx & 127);
        int b  = (int)(idx >> 19);
        float4 v = __ldg(f + b * 128 + j4);
        __stcs(out + idx, v);
    }
}

// ---------------- launch ----------------
extern "C" void kernel_launch(void* const* d_in, const int* in_sizes, int n_in,
                              void* d_out, int out_size) {
    const int*   tok = (const int*)d_in[0];
    const float* r1w = (const float*)d_in[1];
    const float* r1b = (const float*)d_in[2];
    const float* r2w = (const float*)d_in[3];
    const float* r2b = (const float*)d_in[4];
    const float* h1w = (const float*)d_in[5];
    const float* h1b = (const float*)d_in[6];
    const float* h2w = (const float*)d_in[7];
    const float* h2b = (const float*)d_in[8];
    const float* m1w = (const float*)d_in[9];
    const float* m1b = (const float*)d_in[10];
    const float* m2w = (const float*)d_in[11];
    const float* m2b = (const float*)d_in[12];
    const float* d1w = (const float*)d_in[13];
    const float* d1b = (const float*)d_in[14];
    const float* d2w = (const float*)d_in[15];
    const float* d2b = (const float*)d_in[16];
    const float* fcw = (const float*)d_in[17];
    const float* fcb = (const float*)d_in[18];

    prep_kernel<<<96, 256>>>(r1w, r2w, h1w, h2w, m1w, m2w, d1w, d2w);
    branches_kernel<<<3584, 256>>>(tok, r1b, r2b, h1b, h2b, m1b, m2b, d1b, d2b);
    final_kernel<<<BATCH, 256>>>(fcw, fcb);
    broadcast_kernel<<<8192, 256>>>((float4*)d_out);
}

// round 13
// speedup vs baseline: 1.0015x; 1.0006x over previous
#include <cuda_runtime.h>

#define BATCH 32
#define SEQ   4096

typedef unsigned long long ull;

// ---------------- packed f32x2 helpers ----------------
__device__ __forceinline__ void fma2(ull& d, ull a, ull b) {
    asm("fma.rn.f32x2 %0, %1, %2, %0;" : "+l"(d) : "l"(a), "l"(b));
}
__device__ __forceinline__ float2 upk(ull v) {
    float2 f;
    asm("mov.b64 {%0, %1}, %2;" : "=f"(f.x), "=f"(f.y) : "l"(v));
    return f;
}

// ---------------- device scratch (no allocation) ----------------
// transposed first-layer weights: [k][token][o]
__device__ __align__(16) float g_wT_h[12][128][64];
__device__ __align__(16) float g_wT_m[5][128][64];
__device__ __align__(16) float g_wT_d[4][6][16];
__device__ __align__(16) float g_wT_r[8][32];

// transposed second-layer weights: [o][k][c]
__device__ __align__(16) float g_w2_h[32][8][64];
__device__ __align__(16) float g_w2_m[32][3][64];
__device__ __align__(16) float g_w2_r[64][4][32];
__device__ __align__(16) float g_w2_d[16][3][16];

// pooled partials
__device__ float g_part_r[BATCH][16][64];   // 16 chunks of 64 out-l
__device__ float g_part_h[BATCH][32][32];   // 32 chunks of 64 out-l
__device__ float g_part_m[BATCH][32][32];   // 32 chunks of 128 out-l
__device__ float g_dpool [BATCH][128][16];
__device__ __align__(16) float g_feats[BATCH][512];

// ---------------- weight prep (tiny) ----------------
__global__ void prep_kernel(const float* __restrict__ r1w, const float* __restrict__ r2w,
                            const float* __restrict__ h1w, const float* __restrict__ h2w,
                            const float* __restrict__ m1w, const float* __restrict__ m2w,
                            const float* __restrict__ d1w, const float* __restrict__ d2w) {
    int stride = gridDim.x * blockDim.x;
    int tid = blockIdx.x * blockDim.x + threadIdx.x;
    for (int i = tid; i < 64*128*12; i += stride) {
        int o = i / (128*12), r = i % (128*12), t = r / 12, k = r % 12;
        g_wT_h[k][t][o] = h1w[i];
    }
    for (int i = tid; i < 64*128*5; i += stride) {
        int o = i / 640, r = i % 640, t = r / 5, k = r % 5;
        g_wT_m[k][t][o] = m1w[i];
    }
    for (int i = tid; i < 16*6*4; i += stride) {
        int o = i / 24, r = i % 24, v = r / 4, k = r % 4;
        g_wT_d[k][v][o] = d1w[i];
    }
    for (int i = tid; i < 32*8; i += stride) {
        int o = i / 8, k = i % 8;
        g_wT_r[k][o] = r1w[i];
    }
    for (int i = tid; i < 32*64*8; i += stride) {
        int o = i / 512, r = i % 512, c = r / 8, k = r % 8;
        g_w2_h[o][k][c] = h2w[i];
    }
    for (int i = tid; i < 32*64*3; i += stride) {
        int o = i / 192, r = i % 192, c = r / 3, k = r % 3;
        g_w2_m[o][k][c] = m2w[i];
    }
    for (int i = tid; i < 64*32*4; i += stride) {
        int o = i / 128, r = i % 128, c = r / 4, k = r % 4;
        g_w2_r[o][k][c] = r2w[i];
    }
    for (int i = tid; i < 16*16*3; i += stride) {
        int o = i / 48, r = i % 48, c = r / 3, k = r % 3;
        g_w2_d[o][k][c] = d2w[i];
    }
}

// ---------------- fused branch mega-kernel ----------------
// blocks [0,1024): harmony   (b, chunk of 64 out-l;  32 chunks)
// blocks [1024,2048): melody (b, chunk of 128 out-l; 32 chunks)
// blocks [2048,2560): rhythm (b, chunk of 64 out-l;  16 chunks)
// blocks [2560,3584): dynamics (b, group of 4 q-bins; 32 groups)
__global__ void __launch_bounds__(256) branches_kernel(
    const int* __restrict__ tok,
    const float* __restrict__ r1b, const float* __restrict__ r2b,
    const float* __restrict__ h1b, const float* __restrict__ h2b,
    const float* __restrict__ m1b, const float* __restrict__ m2b,
    const float* __restrict__ d1b, const float* __restrict__ d2b)
{
    __shared__ __align__(16) float s_x[8576];   // conv1 tile, [pos][C]
    __shared__ __align__(16) float s_aux[272];  // tokens / ts window
    const int tid = threadIdx.x;
    const int bid = blockIdx.x;
    const int lane = tid & 31;
    const int wrp  = tid >> 5;

    if (bid < 1024) {
        // ================= HARMONY =================
        const int b = bid >> 5, chunk = bid & 31;
        const int L0 = chunk * 64;
        const int P0 = 2 * L0 - 3;          // conv1 pos base, 134 positions
        int* stok = (int*)s_aux;
        for (int j = tid; j < 145; j += 256) {
            int p = P0 - 6 + j;
            stok[j] = ((unsigned)p < (unsigned)SEQ) ? tok[b * SEQ + p] : -1;
        }
        __syncthreads();
        // conv1 into smem: 134 pos x 64 ch
        for (int t = tid; t < 134 * 16; t += 256) {
            int i = t >> 4, o4 = t & 15;
            int p = P0 + i;
            float4 acc = make_float4(0.f, 0.f, 0.f, 0.f);
            if ((unsigned)p < 4097u) {
                acc = __ldg(reinterpret_cast<const float4*>(h1b) + o4);
                #pragma unroll
                for (int k = 0; k < 12; k++) {
                    int tkn = stok[i + k];
                    if ((unsigned)tkn < 128u) {
                        float4 w = *reinterpret_cast<const float4*>(&g_wT_h[k][tkn][o4 * 4]);
                        acc.x += w.x; acc.y += w.y; acc.z += w.z; acc.w += w.w;
                    }
                }
                acc.x = fmaxf(acc.x, 0.f); acc.y = fmaxf(acc.y, 0.f);
                acc.z = fmaxf(acc.z, 0.f); acc.w = fmaxf(acc.w, 0.f);
            }
            *reinterpret_cast<float4*>(&s_x[(i * 16 + o4) * 4]) = acc;
        }
        __syncthreads();
        // conv2: lane -> 2 l, warp -> 4 o. i = 4*lane + 2d + k.
        const int ob = wrp * 4;
        const int ib = 4 * lane;
        ull acc[4][2] = {{0,0},{0,0},{0,0},{0,0}};
        #pragma unroll
        for (int c4 = 0; c4 < 16; c4++) {
            ulonglong2 in[10];
            #pragma unroll
            for (int r = 0; r < 10; r++)
                in[r] = *reinterpret_cast<const ulonglong2*>(&s_x[((ib + r) * 16 + c4) * 4]);
            #pragma unroll
            for (int k = 0; k < 8; k++) {
                #pragma unroll
                for (int o = 0; o < 4; o++) {
                    ulonglong2 ww = __ldg(reinterpret_cast<const ulonglong2*>(&g_w2_h[ob + o][k][c4 * 4]));
                    fma2(acc[o][0], ww.x, in[k].x);
                    fma2(acc[o][0], ww.y, in[k].y);
                    fma2(acc[o][1], ww.x, in[k + 2].x);
                    fma2(acc[o][1], ww.y, in[k + 2].y);
                }
            }
        }
        #pragma unroll
        for (int o = 0; o < 4; o++) {
            float bo = __ldg(h2b + ob + o);
            float2 f0 = upk(acc[o][0]), f1 = upk(acc[o][1]);
            float s = fmaxf(f0.x + f0.y + bo, 0.f) + fmaxf(f1.x + f1.y + bo, 0.f);
            #pragma unroll
            for (int off = 16; off > 0; off >>= 1)
                s += __shfl_down_sync(0xffffffffu, s, off);
            if (lane == 0) g_part_h[b][chunk][ob + o] = s;
        }
    } else if (bid < 2048) {
        // ================= MELODY =================
        const int idx = bid - 1024;
        const int b = idx >> 5, chunk = idx & 31;
        const int L0 = chunk * 128;
        const int P0 = L0 - 1;              // 130 positions
        int* stok = (int*)s_aux;
        for (int j = tid; j < 134; j += 256) {
            int p = P0 - 2 + j;
            stok[j] = ((unsigned)p < (unsigned)SEQ) ? tok[b * SEQ + p] : -1;
        }
        __syncthreads();
        for (int t = tid; t < 130 * 16; t += 256) {
            int i = t >> 4, o4 = t & 15;
            int p = P0 + i;
            float4 acc = make_float4(0.f, 0.f, 0.f, 0.f);
            if ((unsigned)p < 4096u) {
                acc = __ldg(reinterpret_cast<const float4*>(m1b) + o4);
                #pragma unroll
                for (int k = 0; k < 5; k++) {
                    int tkn = stok[i + k];
                    if ((unsigned)tkn < 128u) {
                        float4 w = *reinterpret_cast<const float4*>(&g_wT_m[k][tkn][o4 * 4]);
                        acc.x += w.x; acc.y += w.y; acc.z += w.z; acc.w += w.w;
                    }
                }
                acc.x = fmaxf(acc.x, 0.f); acc.y = fmaxf(acc.y, 0.f);
                acc.z = fmaxf(acc.z, 0.f); acc.w = fmaxf(acc.w, 0.f);
            }
            *reinterpret_cast<float4*>(&s_x[(i * 16 + o4) * 4]) = acc;
        }
        __syncthreads();
        // conv2: lane -> 4 l, warp -> 4 o. i = 4*lane + d + k.
        const int ob = wrp * 4;
        const int ib = 4 * lane;
        ull acc[4][4] = {};
        #pragma unroll
        for (int c4 = 0; c4 < 16; c4++) {
            ulonglong2 in[7];
            #pragma unroll
            for (int r = 0; r < 7; r++)
                in[r] = *reinterpret_cast<const ulonglong2*>(&s_x[((ib + r) * 16 + c4) * 4]);
            #pragma unroll
            for (int k = 0; k < 3; k++) {
                #pragma unroll
                for (int o = 0; o < 4; o++) {
                    ulonglong2 ww = __ldg(reinterpret_cast<const ulonglong2*>(&g_w2_m[ob + o][k][c4 * 4]));
                    #pragma unroll
                    for (int d = 0; d < 4; d++) {
                        fma2(acc[o][d], ww.x, in[k + d].x);
                        fma2(acc[o][d], ww.y, in[k + d].y);
                    }
                }
            }
        }
        #pragma unroll
        for (int o = 0; o < 4; o++) {
            float bo = __ldg(m2b + ob + o);
            float s = 0.f;
            #pragma unroll
            for (int d = 0; d < 4; d++) {
                float2 f = upk(acc[o][d]);
                s += fmaxf(f.x + f.y + bo, 0.f);
            }
            #pragma unroll
            for (int off = 16; off > 0; off >>= 1)
                s += __shfl_down_sync(0xffffffffu, s, off);
            if (lane == 0) g_part_m[b][chunk][ob + o] = s;
        }
    } else if (bid < 2560) {
        // ================= RHYTHM =================
        const int idx = bid - 2048;
        const int b = idx >> 4, chunk = idx & 15;
        const int L0 = chunk * 64;
        const int P0 = 2 * L0 - 1;          // 131 r1 positions
        const int T0 = 2 * P0 - 3;          // ts window base, 268 values
        for (int j = tid; j < 268; j += 256) {
            int tp = T0 + j;
            float v = 0.f;
            if ((unsigned)tp < (unsigned)SEQ) {
                int t = tok[b * SEQ + tp];
                v = (t >= 256 && t < 768) ? 1.f : 0.f;
            }
            s_aux[j] = v;
        }
        __syncthreads();
        // r1 conv into smem: 131 pos x 32 ch
        for (int t = tid; t < 131 * 8; t += 256) {
            int i = t >> 3, o4 = t & 7;
            int p = P0 + i;
            float4 acc = make_float4(0.f, 0.f, 0.f, 0.f);
            if ((unsigned)p < 2048u) {
                acc = __ldg(reinterpret_cast<const float4*>(r1b) + o4);
                #pragma unroll
                for (int k = 0; k < 8; k++) {
                    float tv = s_aux[2 * i + k];
                    float4 w = *reinterpret_cast<const float4*>(&g_wT_r[k][o4 * 4]);
                    acc.x = fmaf(tv, w.x, acc.x);
                    acc.y = fmaf(tv, w.y, acc.y);
                    acc.z = fmaf(tv, w.z, acc.z);
                    acc.w = fmaf(tv, w.w, acc.w);
                }
                acc.x = fmaxf(acc.x, 0.f); acc.y = fmaxf(acc.y, 0.f);
                acc.z = fmaxf(acc.z, 0.f); acc.w = fmaxf(acc.w, 0.f);
            }
            *reinterpret_cast<float4*>(&s_x[(i * 8 + o4) * 4]) = acc;
        }
        __syncthreads();
        // conv2: lane -> 2 l, warp -> 8 o. i = 4*lane + 2d + k, k in [0,4).
        const int ob = wrp * 8;
        const int ib = 4 * lane;
        ull acc[8][2] = {};
        #pragma unroll
        for (int c4 = 0; c4 < 8; c4++) {
            ulonglong2 in[6];
            #pragma unroll
            for (int r = 0; r < 6; r++)
                in[r] = *reinterpret_cast<const ulonglong2*>(&s_x[((ib + r) * 8 + c4) * 4]);
            #pragma unroll
            for (int k = 0; k < 4; k++) {
                #pragma unroll
                for (int o = 0; o < 8; o++) {
                    ulonglong2 ww = __ldg(reinterpret_cast<const ulonglong2*>(&g_w2_r[ob + o][k][c4 * 4]));
                    fma2(acc[o][0], ww.x, in[k].x);
                    fma2(acc[o][0], ww.y, in[k].y);
                    fma2(acc[o][1], ww.x, in[k + 2].x);
                    fma2(acc[o][1], ww.y, in[k + 2].y);
                }
            }
        }
        #pragma unroll
        for (int o = 0; o < 8; o++) {
            float bo = __ldg(r2b + ob + o);
            float2 f0 = upk(acc[o][0]), f1 = upk(acc[o][1]);
            float s = fmaxf(f0.x + f0.y + bo, 0.f) + fmaxf(f1.x + f1.y + bo, 0.f);
            #pragma unroll
            for (int off = 16; off > 0; off >>= 1)
                s += __shfl_down_sync(0xffffffffu, s, off);
            if (lane == 0) g_part_r[b][chunk][ob + o] = s;
        }
    } else {
        // ================= DYNAMICS =================
        const int idx = bid - 2560;
        const int b = idx >> 5, qg = idx & 31;
        const int q0 = qg * 4;
        const int s_all = (q0 * 4097) >> 7;
        const int e_all = ((q0 + 4) * 4097 + 127) >> 7;
        const int P0 = s_all - 1;
        const int PN = e_all - s_all + 2;   // <= 131
        int* stok = (int*)s_aux;
        for (int j = tid; j < PN + 3; j += 256) {
            int p = P0 - 2 + j;
            int v = -1;
            if ((unsigned)p < (unsigned)SEQ) {
                int t = tok[b * SEQ + p];
                if (t >= 768) v = min(t - 768, 5);
            }
            stok[j] = v;
        }
        __syncthreads();
        // d1 conv into smem: PN pos x 16 ch
        for (int t = tid; t < PN * 4; t += 256) {
            int i = t >> 2, o4 = t & 3;
            int p = P0 + i;
            float4 acc = make_float4(0.f, 0.f, 0.f, 0.f);
            if ((unsigned)p < 4097u) {
                acc = __ldg(reinterpret_cast<const float4*>(d1b) + o4);
                #pragma unroll
                for (int k = 0; k < 4; k++) {
                    int v = stok[i + k];
                    if (v >= 0) {
                        float4 w = *reinterpret_cast<const float4*>(&g_wT_d[k][v][o4 * 4]);
                        acc.x += w.x; acc.y += w.y; acc.z += w.z; acc.w += w.w;
                    }
                }
                acc.x = fmaxf(acc.x, 0.f); acc.y = fmaxf(acc.y, 0.f);
                acc.z = fmaxf(acc.z, 0.f); acc.w = fmaxf(acc.w, 0.f);
            }
            *reinterpret_cast<float4*>(&s_x[(i * 4 + o4) * 4]) = acc;
        }
        __syncthreads();
        // d2 conv + adaptive pool: 4 sub-bins x (16 o x 4 j)
        const int qsub = tid >> 6, r = tid & 63;
        const int o = r >> 2, j = r & 3;
        const int q = q0 + qsub;
        const int s0 = (q * 4097) >> 7;
        const int e0 = ((q + 1) * 4097 + 127) >> 7;
        const float bo = __ldg(d2b + o);
        float sum = 0.f;
        for (int l = s0 + j; l < e0; l += 4) {
            ull a2 = 0;
            #pragma unroll
            for (int k = 0; k < 3; k++) {
                int i = l - 1 + k - P0;
                const ull* xr = reinterpret_cast<const ull*>(&s_x[i * 16]);
                const ull* wr = reinterpret_cast<const ull*>(&g_w2_d[o][k][0]);
                #pragma unroll
                for (int c2 = 0; c2 < 8; c2++)
                    fma2(a2, __ldg(wr + c2), xr[c2]);
            }
            float2 f = upk(a2);
            sum += fmaxf(f.x + f.y + bo, 0.f);
        }
        sum += __shfl_down_sync(0xffffffffu, sum, 2);
        sum += __shfl_down_sync(0xffffffffu, sum, 1);
        if (j == 0) g_dpool[b][q][o] = sum / (float)(e0 - s0);
    }
}

// ---------------- second-stage pooling + FC ----------------
__global__ void __launch_bounds__(256) final_kernel(const float* __restrict__ fcw,
                                                    const float* __restrict__ fcb) {
    __shared__ float comb[512];
    int b = blockIdx.x, tid = threadIdx.x;
    for (int idx = tid; idx < 512; idx += 256) {
        float v;
        if (idx < 128) {                       // rhythm
            int o = idx >> 1, hf = idx & 1; float s = 0.f;
            #pragma unroll
            for (int c = 0; c < 8; c++) s += g_part_r[b][hf * 8 + c][o];
            v = s * (1.f / 512.f);
        } else if (idx < 256) {                // harmony
            int i = idx - 128; int o = i >> 2, qk = i & 3; float s = 0.f;
            #pragma unroll
            for (int c = 0; c < 8; c++) s += g_part_h[b][qk * 8 + c][o];
            v = s * (1.f / 512.f);
        } else if (idx < 384) {                // melody
            int i = idx - 256; int o = i >> 2, qk = i & 3; float s = 0.f;
            #pragma unroll
            for (int c = 0; c < 8; c++) s += g_part_m[b][qk * 8 + c][o];
            v = s * (1.f / 1024.f);
        } else {                               // dynamics
            int i = idx - 384; int o = i >> 3, pk = i & 7; float s = 0.f;
            #pragma unroll
            for (int c = 0; c < 16; c++) s += g_dpool[b][pk * 16 + c][o];
            v = s * (1.f / 16.f);
        }
        comb[idx] = v;
    }
    __syncthreads();
    const float4* cw = reinterpret_cast<const float4*>(comb);
    for (int j = tid; j < 512; j += 256) {
        float acc = __ldg(fcb + j);
        const float4* wr = reinterpret_cast<const float4*>(fcw + (size_t)j * 512);
        #pragma unroll 4
        for (int i4 = 0; i4 < 128; i4++) {
            float4 w = __ldg(wr + i4);
            float4 c = cw[i4];
            acc = fmaf(w.x, c.x, acc);
            acc = fmaf(w.y, c.y, acc);
            acc = fmaf(w.z, c.z, acc);
            acc = fmaf(w.w, c.w, acc);
        }
        g_feats[b][j] = acc;
    }
}

// ---------------- broadcast feats -> out[b][s][512] ----------------
__global__ void __launch_bounds__(256) broadcast_kernel(float4* __restrict__ out) {
    const float4* f = reinterpret_cast<const float4*>(&g_feats[0][0]);
    const long long total = (long long)BATCH * SEQ * 128;
    long long stride = (long long)gridDim.x * blockDim.x;
    for (long long idx = (long long)blockIdx.x * blockDim.x + threadIdx.x; idx < total; idx += stride) {
        int j4 = (int)(idx & 127);
        int b  = (int)(idx >> 19);
        float4 v = __ldg(f + b * 128 + j4);
        __stcs(out + idx, v);
    }
}

// ---------------- launch ----------------
extern "C" void kernel_launch(void* const* d_in, const int* in_sizes, int n_in,
                              void* d_out, int out_size) {
    const int*   tok = (const int*)d_in[0];
    const float* r1w = (const float*)d_in[1];
    const float* r1b = (const float*)d_in[2];
    const float* r2w = (const float*)d_in[3];
    const float* r2b = (const float*)d_in[4];
    const float* h1w = (const float*)d_in[5];
    const float* h1b = (const float*)d_in[6];
    const float* h2w = (const float*)d_in[7];
    const float* h2b = (const float*)d_in[8];
    const float* m1w = (const float*)d_in[9];
    const float* m1b = (const float*)d_in[10];
    const float* m2w = (const float*)d_in[11];
    const float* m2b = (const float*)d_in[12];
    const float* d1w = (const float*)d_in[13];
    const float* d1b = (const float*)d_in[14];
    const float* d2w = (const float*)d_in[15];
    const float* d2b = (const float*)d_in[16];
    const float* fcw = (const float*)d_in[17];
    const float* fcb = (const float*)d_in[18];

    prep_kernel<<<96, 256>>>(r1w, r2w, h1w, h2w, m1w, m2w, d1w, d2w);
    branches_kernel<<<3584, 256>>>(tok, r1b, r2b, h1b, h2b, m1b, m2b, d1b, d2b);
    final_kernel<<<BATCH, 256>>>(fcw, fcb);
    broadcast_kernel<<<8192, 256>>>((float4*)d_out);
}

// round 14
// speedup vs baseline: 1.0017x; 1.0003x over previous
#include <cuda_runtime.h>

#define BATCH 32
#define SEQ   4096

typedef unsigned long long ull;

// ---------------- packed f32x2 helpers ----------------
__device__ __forceinline__ void fma2(ull& d, ull a, ull b) {
    asm("fma.rn.f32x2 %0, %1, %2, %0;" : "+l"(d) : "l"(a), "l"(b));
}
__device__ __forceinline__ float2 upk(ull v) {
    float2 f;
    asm("mov.b64 {%0, %1}, %2;" : "=f"(f.x), "=f"(f.y) : "l"(v));
    return f;
}

// ---------------- device scratch (no allocation) ----------------
// transposed first-layer weights: [k][token][o]
__device__ __align__(16) float g_wT_h[12][128][64];
__device__ __align__(16) float g_wT_m[5][128][64];
__device__ __align__(16) float g_wT_d[4][6][16];
__device__ __align__(16) float g_wT_r[8][32];

// transposed second-layer weights: [o][k][c]
__device__ __align__(16) float g_w2_h[32][8][64];
__device__ __align__(16) float g_w2_m[32][3][64];
__device__ __align__(16) float g_w2_r[64][4][32];
__device__ __align__(16) float g_w2_d[16][3][16];

// pooled partials
__device__ float g_part_r[BATCH][16][64];   // 16 chunks of 64 out-l
__device__ float g_part_h[BATCH][32][32];   // 32 chunks of 64 out-l
__device__ float g_part_m[BATCH][32][32];   // 32 chunks of 128 out-l
__device__ float g_dpool [BATCH][128][16];
__device__ __align__(16) float g_feats[BATCH][512];

// ---------------- weight prep (tiny) ----------------
__global__ void prep_kernel(const float* __restrict__ r1w, const float* __restrict__ r2w,
                            const float* __restrict__ h1w, const float* __restrict__ h2w,
                            const float* __restrict__ m1w, const float* __restrict__ m2w,
                            const float* __restrict__ d1w, const float* __restrict__ d2w) {
    int stride = gridDim.x * blockDim.x;
    int tid = blockIdx.x * blockDim.x + threadIdx.x;
    for (int i = tid; i < 64*128*12; i += stride) {
        int o = i / (128*12), r = i % (128*12), t = r / 12, k = r % 12;
        g_wT_h[k][t][o] = h1w[i];
    }
    for (int i = tid; i < 64*128*5; i += stride) {
        int o = i / 640, r = i % 640, t = r / 5, k = r % 5;
        g_wT_m[k][t][o] = m1w[i];
    }
    for (int i = tid; i < 16*6*4; i += stride) {
        int o = i / 24, r = i % 24, v = r / 4, k = r % 4;
        g_wT_d[k][v][o] = d1w[i];
    }
    for (int i = tid; i < 32*8; i += stride) {
        int o = i / 8, k = i % 8;
        g_wT_r[k][o] = r1w[i];
    }
    for (int i = tid; i < 32*64*8; i += stride) {
        int o = i / 512, r = i % 512, c = r / 8, k = r % 8;
        g_w2_h[o][k][c] = h2w[i];
    }
    for (int i = tid; i < 32*64*3; i += stride) {
        int o = i / 192, r = i % 192, c = r / 3, k = r % 3;
        g_w2_m[o][k][c] = m2w[i];
    }
    for (int i = tid; i < 64*32*4; i += stride) {
        int o = i / 128, r = i % 128, c = r / 4, k = r % 4;
        g_w2_r[o][k][c] = r2w[i];
    }
    for (int i = tid; i < 16*16*3; i += stride) {
        int o = i / 48, r = i % 48, c = r / 3, k = r % 3;
        g_w2_d[o][k][c] = d2w[i];
    }
}

// ---------------- fused branch mega-kernel ----------------
// blocks [0,1024): harmony   (b, chunk of 64 out-l;  32 chunks)
// blocks [1024,2048): melody (b, chunk of 128 out-l; 32 chunks)
// blocks [2048,2560): rhythm (b, chunk of 64 out-l;  16 chunks)
// blocks [2560,3584): dynamics (b, group of 4 q-bins; 32 groups)
__global__ void __launch_bounds__(256) branches_kernel(
    const int* __restrict__ tok,
    const float* __restrict__ r1b, const float* __restrict__ r2b,
    const float* __restrict__ h1b, const float* __restrict__ h2b,
    const float* __restrict__ m1b, const float* __restrict__ m2b,
    const float* __restrict__ d1b, const float* __restrict__ d2b)
{
    __shared__ __align__(16) float s_x[8576];   // conv1 tile, [pos][C]
    __shared__ __align__(16) float s_aux[272];  // tokens / ts window
    const int tid = threadIdx.x;
    const int bid = blockIdx.x;
    const int lane = tid & 31;
    const int wrp  = tid >> 5;

    if (bid < 1024) {
        // ================= HARMONY =================
        const int b = bid >> 5, chunk = bid & 31;
        const int L0 = chunk * 64;
        const int P0 = 2 * L0 - 3;          // conv1 pos base, 134 positions
        int* stok = (int*)s_aux;
        for (int j = tid; j < 145; j += 256) {
            int p = P0 - 6 + j;
            stok[j] = ((unsigned)p < (unsigned)SEQ) ? tok[b * SEQ + p] : -1;
        }
        __syncthreads();
        // conv1 into smem: 134 pos x 64 ch
        for (int t = tid; t < 134 * 16; t += 256) {
            int i = t >> 4, o4 = t & 15;
            int p = P0 + i;
            float4 acc = make_float4(0.f, 0.f, 0.f, 0.f);
            if ((unsigned)p < 4097u) {
                acc = __ldg(reinterpret_cast<const float4*>(h1b) + o4);
                #pragma unroll
                for (int k = 0; k < 12; k++) {
                    int tkn = stok[i + k];
                    if ((unsigned)tkn < 128u) {
                        float4 w = *reinterpret_cast<const float4*>(&g_wT_h[k][tkn][o4 * 4]);
                        acc.x += w.x; acc.y += w.y; acc.z += w.z; acc.w += w.w;
                    }
                }
                acc.x = fmaxf(acc.x, 0.f); acc.y = fmaxf(acc.y, 0.f);
                acc.z = fmaxf(acc.z, 0.f); acc.w = fmaxf(acc.w, 0.f);
            }
            *reinterpret_cast<float4*>(&s_x[(i * 16 + o4) * 4]) = acc;
        }
        __syncthreads();
        // conv2: lane -> 2 l, warp -> 4 o. i = 4*lane + 2d + k.
        const int ob = wrp * 4;
        const int ib = 4 * lane;
        ull acc[4][2] = {{0,0},{0,0},{0,0},{0,0}};
        #pragma unroll
        for (int c4 = 0; c4 < 16; c4++) {
            ulonglong2 in[10];
            #pragma unroll
            for (int r = 0; r < 10; r++)
                in[r] = *reinterpret_cast<const ulonglong2*>(&s_x[((ib + r) * 16 + c4) * 4]);
            #pragma unroll
            for (int k = 0; k < 8; k++) {
                #pragma unroll
                for (int o = 0; o < 4; o++) {
                    ulonglong2 ww = __ldg(reinterpret_cast<const ulonglong2*>(&g_w2_h[ob + o][k][c4 * 4]));
                    fma2(acc[o][0], ww.x, in[k].x);
                    fma2(acc[o][0], ww.y, in[k].y);
                    fma2(acc[o][1], ww.x, in[k + 2].x);
                    fma2(acc[o][1], ww.y, in[k + 2].y);
                }
            }
        }
        #pragma unroll
        for (int o = 0; o < 4; o++) {
            float bo = __ldg(h2b + ob + o);
            float2 f0 = upk(acc[o][0]), f1 = upk(acc[o][1]);
            float s = fmaxf(f0.x + f0.y + bo, 0.f) + fmaxf(f1.x + f1.y + bo, 0.f);
            #pragma unroll
            for (int off = 16; off > 0; off >>= 1)
                s += __shfl_down_sync(0xffffffffu, s, off);
            if (lane == 0) g_part_h[b][chunk][ob + o] = s;
        }
    } else if (bid < 2048) {
        // ================= MELODY =================
        const int idx = bid - 1024;
        const int b = idx >> 5, chunk = idx & 31;
        const int L0 = chunk * 128;
        const int P0 = L0 - 1;              // 130 positions
        int* stok = (int*)s_aux;
        for (int j = tid; j < 134; j += 256) {
            int p = P0 - 2 + j;
            stok[j] = ((unsigned)p < (unsigned)SEQ) ? tok[b * SEQ + p] : -1;
        }
        __syncthreads();
        for (int t = tid; t < 130 * 16; t += 256) {
            int i = t >> 4, o4 = t & 15;
            int p = P0 + i;
            float4 acc = make_float4(0.f, 0.f, 0.f, 0.f);
            if ((unsigned)p < 4096u) {
                acc = __ldg(reinterpret_cast<const float4*>(m1b) + o4);
                #pragma unroll
                for (int k = 0; k < 5; k++) {
                    int tkn = stok[i + k];
                    if ((unsigned)tkn < 128u) {
                        float4 w = *reinterpret_cast<const float4*>(&g_wT_m[k][tkn][o4 * 4]);
                        acc.x += w.x; acc.y += w.y; acc.z += w.z; acc.w += w.w;
                    }
                }
                acc.x = fmaxf(acc.x, 0.f); acc.y = fmaxf(acc.y, 0.f);
                acc.z = fmaxf(acc.z, 0.f); acc.w = fmaxf(acc.w, 0.f);
            }
            *reinterpret_cast<float4*>(&s_x[(i * 16 + o4) * 4]) = acc;
        }
        __syncthreads();
        // conv2: lane -> 4 l, warp -> 4 o. i = 4*lane + d + k.
        const int ob = wrp * 4;
        const int ib = 4 * lane;
        ull acc[4][4] = {};
        #pragma unroll
        for (int c4 = 0; c4 < 16; c4++) {
            ulonglong2 in[7];
            #pragma unroll
            for (int r = 0; r < 7; r++)
                in[r] = *reinterpret_cast<const ulonglong2*>(&s_x[((ib + r) * 16 + c4) * 4]);
            #pragma unroll
            for (int k = 0; k < 3; k++) {
                #pragma unroll
                for (int o = 0; o < 4; o++) {
                    ulonglong2 ww = __ldg(reinterpret_cast<const ulonglong2*>(&g_w2_m[ob + o][k][c4 * 4]));
                    #pragma unroll
                    for (int d = 0; d < 4; d++) {
                        fma2(acc[o][d], ww.x, in[k + d].x);
                        fma2(acc[o][d], ww.y, in[k + d].y);
                    }
                }
            }
        }
        #pragma unroll
        for (int o = 0; o < 4; o++) {
            float bo = __ldg(m2b + ob + o);
            float s = 0.f;
            #pragma unroll
            for (int d = 0; d < 4; d++) {
                float2 f = upk(acc[o][d]);
                s += fmaxf(f.x + f.y + bo, 0.f);
            }
            #pragma unroll
            for (int off = 16; off > 0; off >>= 1)
                s += __shfl_down_sync(0xffffffffu, s, off);
            if (lane == 0) g_part_m[b][chunk][ob + o] = s;
        }
    } else if (bid < 2560) {
        // ================= RHYTHM =================
        const int idx = bid - 2048;
        const int b = idx >> 4, chunk = idx & 15;
        const int L0 = chunk * 64;
        const int P0 = 2 * L0 - 1;          // 131 r1 positions
        const int T0 = 2 * P0 - 3;          // ts window base, 268 values
        for (int j = tid; j < 268; j += 256) {
            int tp = T0 + j;
            float v = 0.f;
            if ((unsigned)tp < (unsigned)SEQ) {
                int t = tok[b * SEQ + tp];
                v = (t >= 256 && t < 768) ? 1.f : 0.f;
            }
            s_aux[j] = v;
        }
        __syncthreads();
        // r1 conv into smem: 131 pos x 32 ch
        for (int t = tid; t < 131 * 8; t += 256) {
            int i = t >> 3, o4 = t & 7;
            int p = P0 + i;
            float4 acc = make_float4(0.f, 0.f, 0.f, 0.f);
            if ((unsigned)p < 2048u) {
                acc = __ldg(reinterpret_cast<const float4*>(r1b) + o4);
                #pragma unroll
                for (int k = 0; k < 8; k++) {
                    float tv = s_aux[2 * i + k];
                    float4 w = *reinterpret_cast<const float4*>(&g_wT_r[k][o4 * 4]);
                    acc.x = fmaf(tv, w.x, acc.x);
                    acc.y = fmaf(tv, w.y, acc.y);
                    acc.z = fmaf(tv, w.z, acc.z);
                    acc.w = fmaf(tv, w.w, acc.w);
                }
                acc.x = fmaxf(acc.x, 0.f); acc.y = fmaxf(acc.y, 0.f);
                acc.z = fmaxf(acc.z, 0.f); acc.w = fmaxf(acc.w, 0.f);
            }
            *reinterpret_cast<float4*>(&s_x[(i * 8 + o4) * 4]) = acc;
        }
        __syncthreads();
        // conv2: lane -> 2 l, warp -> 8 o. i = 4*lane + 2d + k, k in [0,4).
        const int ob = wrp * 8;
        const int ib = 4 * lane;
        ull acc[8][2] = {};
        #pragma unroll
        for (int c4 = 0; c4 < 8; c4++) {
            ulonglong2 in[6];
            #pragma unroll
            for (int r = 0; r < 6; r++)
                in[r] = *reinterpret_cast<const ulonglong2*>(&s_x[((ib + r) * 8 + c4) * 4]);
            #pragma unroll
            for (int k = 0; k < 4; k++) {
                #pragma unroll
                for (int o = 0; o < 8; o++) {
                    ulonglong2 ww = __ldg(reinterpret_cast<const ulonglong2*>(&g_w2_r[ob + o][k][c4 * 4]));
                    fma2(acc[o][0], ww.x, in[k].x);
                    fma2(acc[o][0], ww.y, in[k].y);
                    fma2(acc[o][1], ww.x, in[k + 2].x);
                    fma2(acc[o][1], ww.y, in[k + 2].y);
                }
            }
        }
        #pragma unroll
        for (int o = 0; o < 8; o++) {
            float bo = __ldg(r2b + ob + o);
            float2 f0 = upk(acc[o][0]), f1 = upk(acc[o][1]);
            float s = fmaxf(f0.x + f0.y + bo, 0.f) + fmaxf(f1.x + f1.y + bo, 0.f);
            #pragma unroll
            for (int off = 16; off > 0; off >>= 1)
                s += __shfl_down_sync(0xffffffffu, s, off);
            if (lane == 0) g_part_r[b][chunk][ob + o] = s;
        }
    } else {
        // ================= DYNAMICS =================
        const int idx = bid - 2560;
        const int b = idx >> 5, qg = idx & 31;
        const int q0 = qg * 4;
        const int s_all = (q0 * 4097) >> 7;
        const int e_all = ((q0 + 4) * 4097 + 127) >> 7;
        const int P0 = s_all - 1;
        const int PN = e_all - s_all + 2;   // <= 131
        int* stok = (int*)s_aux;
        for (int j = tid; j < PN + 3; j += 256) {
            int p = P0 - 2 + j;
            int v = -1;
            if ((unsigned)p < (unsigned)SEQ) {
                int t = tok[b * SEQ + p];
                if (t >= 768) v = min(t - 768, 5);
            }
            stok[j] = v;
        }
        __syncthreads();
        // d1 conv into smem: PN pos x 16 ch
        for (int t = tid; t < PN * 4; t += 256) {
            int i = t >> 2, o4 = t & 3;
            int p = P0 + i;
            float4 acc = make_float4(0.f, 0.f, 0.f, 0.f);
            if ((unsigned)p < 4097u) {
                acc = __ldg(reinterpret_cast<const float4*>(d1b) + o4);
                #pragma unroll
                for (int k = 0; k < 4; k++) {
                    int v = stok[i + k];
                    if (v >= 0) {
                        float4 w = *reinterpret_cast<const float4*>(&g_wT_d[k][v][o4 * 4]);
                        acc.x += w.x; acc.y += w.y; acc.z += w.z; acc.w += w.w;
                    }
                }
                acc.x = fmaxf(acc.x, 0.f); acc.y = fmaxf(acc.y, 0.f);
                acc.z = fmaxf(acc.z, 0.f); acc.w = fmaxf(acc.w, 0.f);
            }
            *reinterpret_cast<float4*>(&s_x[(i * 4 + o4) * 4]) = acc;
        }
        __syncthreads();
        // d2 conv + adaptive pool: 4 sub-bins x (16 o x 4 j)
        const int qsub = tid >> 6, r = tid & 63;
        const int o = r >> 2, j = r & 3;
        const int q = q0 + qsub;
        const int s0 = (q * 4097) >> 7;
        const int e0 = ((q + 1) * 4097 + 127) >> 7;
        const float bo = __ldg(d2b + o);
        float sum = 0.f;
        for (int l = s0 + j; l < e0; l += 4) {
            ull a2 = 0;
            #pragma unroll
            for (int k = 0; k < 3; k++) {
                int i = l - 1 + k - P0;
                const ull* xr = reinterpret_cast<const ull*>(&s_x[i * 16]);
                const ull* wr = reinterpret_cast<const ull*>(&g_w2_d[o][k][0]);
                #pragma unroll
                for (int c2 = 0; c2 < 8; c2++)
                    fma2(a2, __ldg(wr + c2), xr[c2]);
            }
            float2 f = upk(a2);
            sum += fmaxf(f.x + f.y + bo, 0.f);
        }
        sum += __shfl_down_sync(0xffffffffu, sum, 2);
        sum += __shfl_down_sync(0xffffffffu, sum, 1);
        if (j == 0) g_dpool[b][q][o] = sum / (float)(e0 - s0);
    }
}

// ---------------- second-stage pooling + FC ----------------
__global__ void __launch_bounds__(256) final_kernel(const float* __restrict__ fcw,
                                                    const float* __restrict__ fcb) {
    __shared__ float comb[512];
    int b = blockIdx.x, tid = threadIdx.x;
    for (int idx = tid; idx < 512; idx += 256) {
        float v;
        if (idx < 128) {                       // rhythm
            int o = idx >> 1, hf = idx & 1; float s = 0.f;
            #pragma unroll
            for (int c = 0; c < 8; c++) s += g_part_r[b][hf * 8 + c][o];
            v = s * (1.f / 512.f);
        } else if (idx < 256) {                // harmony
            int i = idx - 128; int o = i >> 2, qk = i & 3; float s = 0.f;
            #pragma unroll
            for (int c = 0; c < 8; c++) s += g_part_h[b][qk * 8 + c][o];
            v = s * (1.f / 512.f);
        } else if (idx < 384) {                // melody
            int i = idx - 256; int o = i >> 2, qk = i & 3; float s = 0.f;
            #pragma unroll
            for (int c = 0; c < 8; c++) s += g_part_m[b][qk * 8 + c][o];
            v = s * (1.f / 1024.f);
        } else {                               // dynamics
            int i = idx - 384; int o = i >> 3, pk = i & 7; float s = 0.f;
            #pragma unroll
            for (int c = 0; c < 16; c++) s += g_dpool[b][pk * 16 + c][o];
            v = s * (1.f / 16.f);
        }
        comb[idx] = v;
    }
    __syncthreads();
    const float4* cw = reinterpret_cast<const float4*>(comb);
    for (int j = tid; j < 512; j += 256) {
        float acc = __ldg(fcb + j);
        const float4* wr = reinterpret_cast<const float4*>(fcw + (size_t)j * 512);
        #pragma unroll 4
        for (int i4 = 0; i4 < 128; i4++) {
            float4 w = __ldg(wr + i4);
            float4 c = cw[i4];
            acc = fmaf(w.x, c.x, acc);
            acc = fmaf(w.y, c.y, acc);
            acc = fmaf(w.z, c.z, acc);
            acc = fmaf(w.w, c.w, acc);
        }
        g_feats[b][j] = acc;
    }
}

// ---------------- broadcast feats -> out[b][s][512] ----------------
__global__ void __launch_bounds__(256) broadcast_kernel(float4* __restrict__ out) {
    const float4* f = reinterpret_cast<const float4*>(&g_feats[0][0]);
    const long long total = (long long)BATCH * SEQ * 128;
    long long stride = (long long)gridDim.x * blockDim.x;
    for (long long idx = (long long)blockIdx.x * blockDim.x + threadIdx.x; idx < total; idx += stride) {
        int j4 = (int)(idx & 127);
        int b  = (int)(idx >> 19);
        float4 v = __ldg(f + b * 128 + j4);
        __stcs(out + idx, v);
    }
}

// ---------------- launch ----------------
extern "C" void kernel_launch(void* const* d_in, const int* in_sizes, int n_in,
                              void* d_out, int out_size) {
    const int*   tok = (const int*)d_in[0];
    const float* r1w = (const float*)d_in[1];
    const float* r1b = (const float*)d_in[2];
    const float* r2w = (const float*)d_in[3];
    const float* r2b = (const float*)d_in[4];
    const float* h1w = (const float*)d_in[5];
    const float* h1b = (const float*)d_in[6];
    const float* h2w = (const float*)d_in[7];
    const float* h2b = (const float*)d_in[8];
    const float* m1w = (const float*)d_in[9];
    const float* m1b = (const float*)d_in[10];
    const float* m2w = (const float*)d_in[11];
    const float* m2b = (const float*)d_in[12];
    const float* d1w = (const float*)d_in[13];
    const float* d1b = (const float*)d_in[14];
    const float* d2w = (const float*)d_in[15];
    const float* d2b = (const float*)d_in[16];
    const float* fcw = (const float*)d_in[17];
    const float* fcb = (const float*)d_in[18];

    prep_kernel<<<96, 256>>>(r1w, r2w, h1w, h2w, m1w, m2w, d1w, d2w);
    branches_kernel<<<3584, 256>>>(tok, r1b, r2b, h1b, h2b, m1b, m2b, d1b, d2b);
    final_kernel<<<BATCH, 256>>>(fcw, fcb);
    broadcast_kernel<<<8192, 256>>>((float4*)d_out);
}